// round 13
// baseline (speedup 1.0000x reference)
#include <cuda_runtime.h>
#include <cuda_bf16.h>
#include <cstdint>
#include <math.h>

// Problem constants
#define BATCH   2
#define S_LEN   2048
#define D_DIM   2048
#define NH      16
#define HD      128
#define LAT     512
#define ROWS_TOT (BATCH * S_LEN)   // 4096
#define KV_W    4096               // merged K|V row width
#define QC_W    2560               // merged Q|c row width (2048 Q + 512 c)

// ---------------------------------------------------------------------------
// Scratch (__device__ globals; allocation-free rule)
// ---------------------------------------------------------------------------
__device__ __nv_bfloat16 g_xhi[ROWS_TOT * D_DIM];
__device__ __nv_bfloat16 g_xlo[ROWS_TOT * D_DIM];
__device__ __nv_bfloat16 g_qchi[ROWS_TOT * QC_W];   // [0,2048)=Q(roped), [2048,2560)=c
__device__ __nv_bfloat16 g_qclo[ROWS_TOT * QC_W];
__device__ __nv_bfloat16 g_kvhi[ROWS_TOT * KV_W];   // [0,2048)=K(roped), [2048,4096)=V
__device__ __nv_bfloat16 g_kvlo[ROWS_TOT * KV_W];
__device__ __nv_bfloat16 g_ohi[ROWS_TOT * D_DIM];
__device__ __nv_bfloat16 g_olo[ROWS_TOT * D_DIM];
__device__ float2 g_cs[S_LEN * (HD / 2)];           // RoPE cos/sin table

// Transposed-weight pool ([N,K] K-major bf16), hi and lo parts.
#define OFF_WQ  0
#define OFF_WDN 4194304
#define OFF_WKU 5242880
#define OFF_WVU 6291456
#define OFF_WO  7340032
#define WT_TOTAL 11534336
__device__ __nv_bfloat16 g_wthi[WT_TOTAL];
__device__ __nv_bfloat16 g_wtlo[WT_TOTAL];

// ---------------------------------------------------------------------------
// PTX helpers (sm_80+ features only — harness targets plain sm_103)
// ---------------------------------------------------------------------------
__device__ __forceinline__ uint32_t smem_u32(const void* p) {
    uint32_t a;
    asm("{ .reg .u64 t; cvta.to.shared.u64 t, %1; cvt.u32.u64 %0, t; }"
        : "=r"(a) : "l"(p));
    return a;
}
__device__ __forceinline__ void cp16(uint32_t dst, const void* src) {
    asm volatile("cp.async.cg.shared.global [%0], [%1], 16;" :: "r"(dst), "l"(src));
}
#define CP_COMMIT() asm volatile("cp.async.commit_group;" ::: "memory")

__device__ __forceinline__ void ldsm4(uint32_t& r0, uint32_t& r1,
                                      uint32_t& r2, uint32_t& r3, uint32_t a) {
    asm volatile("ldmatrix.sync.aligned.m8n8.x4.shared.b16 {%0,%1,%2,%3}, [%4];"
                 : "=r"(r0), "=r"(r1), "=r"(r2), "=r"(r3) : "r"(a));
}
__device__ __forceinline__ void ldsm4t(uint32_t& r0, uint32_t& r1,
                                       uint32_t& r2, uint32_t& r3, uint32_t a) {
    asm volatile("ldmatrix.sync.aligned.m8n8.x4.trans.shared.b16 {%0,%1,%2,%3}, [%4];"
                 : "=r"(r0), "=r"(r1), "=r"(r2), "=r"(r3) : "r"(a));
}
// Non-volatile: pure register op; lets ptxas interleave MMAs to break
// accumulator RAW chains.
__device__ __forceinline__ void mma16816(float* d, const uint32_t* a,
                                         uint32_t b0, uint32_t b1) {
    asm("mma.sync.aligned.m16n8k16.row.col.f32.bf16.bf16.f32 "
        "{%0,%1,%2,%3}, {%4,%5,%6,%7}, {%8,%9}, {%0,%1,%2,%3};"
        : "+f"(d[0]), "+f"(d[1]), "+f"(d[2]), "+f"(d[3])
        : "r"(a[0]), "r"(a[1]), "r"(a[2]), "r"(a[3]), "r"(b0), "r"(b1));
}
__device__ __forceinline__ uint32_t packbf2(__nv_bfloat16 x, __nv_bfloat16 y) {
    __nv_bfloat162 t(x, y);
    return *(uint32_t*)&t;
}

// XOR chunk swizzle for 64B-pitch rows (4 x 16B chunks per row).
__device__ __forceinline__ uint32_t swz64(int row, int chunk) {
    return (uint32_t)(row * 64 + ((chunk ^ ((row >> 1) & 3)) << 4));
}

// ---------------------------------------------------------------------------
// HMMA bf16 hi/lo GEMM (persistent). Round-12 mainloop (known-good).
// ---------------------------------------------------------------------------
#define ST_AHI  0
#define ST_ALO  8192
#define ST_BHI  16384
#define ST_BLO  24576
#define STAGE_B 32768
#define GK_SMEM_DYN (3 * STAGE_B)   // 96 KB
#define GK_GRID 296                 // 2 CTAs x 148 SMs

__global__ __launch_bounds__(256, 2)
void gemm_hilo_kernel(const __nv_bfloat16* __restrict__ Ahi,
                      const __nv_bfloat16* __restrict__ Alo,
                      const __nv_bfloat16* __restrict__ Bhi,
                      const __nv_bfloat16* __restrict__ Blo,
                      float* __restrict__ Cout,
                      __nv_bfloat16* __restrict__ Chi,
                      __nv_bfloat16* __restrict__ Clo,
                      const float2* __restrict__ cstab,
                      int rope_cols,
                      int M, int N, int K, int lda, int ldc)
{
    extern __shared__ char dsm[];
    const uint32_t sbase = smem_u32(dsm);
    const int tid = threadIdx.x, lane = tid & 31, wid = tid >> 5;
    const int wm = wid & 3, wn = wid >> 2;           // 4 x 2 warp grid
    const int lrow = tid >> 1;
    const int lc0  = (tid & 1) * 2;
    const int lr = lane >> 2, lc = (lane & 3) * 2;
    const int nk = K >> 5;
    const int ntx = N >> 7;
    const int ntiles = (M >> 7) * ntx;

    for (int tile = blockIdx.x; tile < ntiles; tile += gridDim.x) {
        const int tyi = tile / ntx;
        const int txi = tile - tyi * ntx;
        const int m0 = tyi * 128, n0 = txi * 128;

        const __nv_bfloat16* gAh = Ahi + (size_t)m0 * lda;
        const __nv_bfloat16* gAl = Alo + (size_t)m0 * lda;
        const __nv_bfloat16* gBh = Bhi + (size_t)n0 * K;
        const __nv_bfloat16* gBl = Blo + (size_t)n0 * K;

        float acc[2][8][4];
#pragma unroll
        for (int mt = 0; mt < 2; mt++)
#pragma unroll
            for (int nt = 0; nt < 8; nt++)
#pragma unroll
                for (int r = 0; r < 4; r++) acc[mt][nt][r] = 0.f;

        auto load_stage = [&](int buf, int kc) {
            const uint32_t st = sbase + buf * STAGE_B;
            const size_t koff = (size_t)kc * 32;
#pragma unroll
            for (int t = 0; t < 2; t++) {
                const int c = lc0 + t;
                const uint32_t doff = swz64(lrow, c);
                cp16(st + ST_AHI + doff, gAh + (size_t)lrow * lda + koff + c * 8);
                cp16(st + ST_ALO + doff, gAl + (size_t)lrow * lda + koff + c * 8);
                cp16(st + ST_BHI + doff, gBh + (size_t)lrow * K + koff + c * 8);
                cp16(st + ST_BLO + doff, gBl + (size_t)lrow * K + koff + c * 8);
            }
            CP_COMMIT();
        };

        load_stage(0, 0);
        if (nk > 1) load_stage(1, 1);

        for (int k = 0; k < nk; k++) {
            if (k + 1 < nk)
                asm volatile("cp.async.wait_group 1;" ::: "memory");
            else
                asm volatile("cp.async.wait_group 0;" ::: "memory");
            __syncthreads();

            if (k + 2 < nk) load_stage((k + 2) % 3, k + 2);

            const uint32_t st = sbase + (k % 3) * STAGE_B;
#pragma unroll
            for (int ks = 0; ks < 2; ks++) {
                uint32_t ah[2][4], al[2][4];
#pragma unroll
                for (int mt = 0; mt < 2; mt++) {
                    const int row = wm * 32 + mt * 16 + (lane & 15);
                    const uint32_t off = swz64(row, ks * 2 + (lane >> 4));
                    ldsm4(ah[mt][0], ah[mt][1], ah[mt][2], ah[mt][3],
                          st + ST_AHI + off);
                    ldsm4(al[mt][0], al[mt][1], al[mt][2], al[mt][3],
                          st + ST_ALO + off);
                }
#pragma unroll
                for (int bp = 0; bp < 4; bp++) {
                    const int rn = wn * 64 + bp * 16 + ((lane >> 4) << 3) + (lane & 7);
                    const uint32_t off = swz64(rn, ks * 2 + ((lane >> 3) & 1));
                    uint32_t bh[4], bl[4];
                    ldsm4(bh[0], bh[1], bh[2], bh[3], st + ST_BHI + off);
                    ldsm4(bl[0], bl[1], bl[2], bl[3], st + ST_BLO + off);
#pragma unroll
                    for (int mt = 0; mt < 2; mt++)
#pragma unroll
                        for (int h = 0; h < 2; h++)
                            mma16816(acc[mt][2 * bp + h], ah[mt], bh[2 * h], bh[2 * h + 1]);
#pragma unroll
                    for (int mt = 0; mt < 2; mt++)
#pragma unroll
                        for (int h = 0; h < 2; h++)
                            mma16816(acc[mt][2 * bp + h], ah[mt], bl[2 * h], bl[2 * h + 1]);
#pragma unroll
                    for (int mt = 0; mt < 2; mt++)
#pragma unroll
                        for (int h = 0; h < 2; h++)
                            mma16816(acc[mt][2 * bp + h], al[mt], bh[2 * h], bh[2 * h + 1]);
                }
            }
        }

        const int rbase = m0 + wm * 32, cbase = n0 + wn * 64;
        if (Cout) {
#pragma unroll
            for (int mt = 0; mt < 2; mt++) {
#pragma unroll
                for (int nt = 0; nt < 8; nt++) {
                    float* d = acc[mt][nt];
                    const size_t r0 = (size_t)(rbase + mt * 16 + lr) * ldc
                                      + cbase + nt * 8 + lc;
                    *(float2*)(Cout + r0)           = make_float2(d[0], d[1]);
                    *(float2*)(Cout + r0 + 8 * ldc) = make_float2(d[2], d[3]);
                }
            }
        } else {
            const bool do_rope = (cstab != nullptr) && (cbase < rope_cols);
#pragma unroll
            for (int mt = 0; mt < 2; mt++) {
#pragma unroll
                for (int nt = 0; nt < 8; nt++) {
                    float* d = acc[mt][nt];
#pragma unroll
                    for (int half = 0; half < 2; half++) {
                        const int row = rbase + mt * 16 + lr + half * 8;
                        const int col = cbase + nt * 8 + lc;
                        float v0 = d[half * 2], v1 = d[half * 2 + 1];
                        if (do_rope) {
                            const int s = row & (S_LEN - 1);
                            const int p = (col & (HD - 1)) >> 1;
                            float2 cs = __ldg(cstab + s * (HD / 2) + p);
                            float r0 = v0 * cs.x - v1 * cs.y;
                            float r1 = v0 * cs.y + v1 * cs.x;
                            v0 = r0; v1 = r1;
                        }
                        __nv_bfloat16 h0 = __float2bfloat16(v0);
                        __nv_bfloat16 h1 = __float2bfloat16(v1);
                        const size_t o = (size_t)row * ldc + col;
                        *(uint32_t*)(Chi + o) = packbf2(h0, h1);
                        *(uint32_t*)(Clo + o) = packbf2(
                            __float2bfloat16(v0 - __bfloat162float(h0)),
                            __float2bfloat16(v1 - __bfloat162float(h1)));
                    }
                }
            }
        }
        __syncthreads();
    }
}

// ---------------------------------------------------------------------------
// Prep kernels
// ---------------------------------------------------------------------------
__global__ void convert_hilo_kernel(const float* __restrict__ in,
                                    __nv_bfloat16* __restrict__ hi,
                                    __nv_bfloat16* __restrict__ lo, int n)
{
    int i = blockIdx.x * blockDim.x + threadIdx.x;
    if (i >= n) return;
    float v = in[i];
    __nv_bfloat16 h = __float2bfloat16(v);
    hi[i] = h;
    lo[i] = __float2bfloat16(v - __bfloat162float(h));
}

__global__ void rope_table_kernel(const float* __restrict__ freqs,
                                  float2* __restrict__ cstab)
{
    int i = blockIdx.x * blockDim.x + threadIdx.x;
    if (i >= S_LEN * (HD / 2)) return;
    float f = freqs[i];
    float sn, cs;
    sincosf(f, &sn, &cs);
    cstab[i] = make_float2(cs, sn);
}

__global__ void transpose_hilo_kernel(const float* __restrict__ W,
                                      __nv_bfloat16* __restrict__ hi,
                                      __nv_bfloat16* __restrict__ lo,
                                      int Kd, int Nd)
{
    __shared__ float t[32][33];
    const int tx = threadIdx.x, ty = threadIdx.y;
    const int k0 = blockIdx.y * 32, n0 = blockIdx.x * 32;
#pragma unroll
    for (int i = 0; i < 4; i++)
        t[ty + i * 8][tx] = W[(size_t)(k0 + ty + i * 8) * Nd + n0 + tx];
    __syncthreads();
#pragma unroll
    for (int i = 0; i < 4; i++) {
        float v = t[tx][ty + i * 8];
        __nv_bfloat16 h = __float2bfloat16(v);
        size_t o = (size_t)(n0 + ty + i * 8) * Kd + k0 + tx;
        hi[o] = h;
        lo[o] = __float2bfloat16(v - __bfloat162float(h));
    }
}

// ---------------------------------------------------------------------------
// HMMA causal flash attention v2: 256 threads, 8 warps in 4(M)x2(N) grid.
// Each warp: 16 q-rows x 32 S-cols. Cross-warp (wn pair) softmax stats via
// smem; partial-O merge through freed K smem at the end. Staggered K/V
// cp.async pipeline retained. 16 warps/SM (2 CTAs x 8).
// ---------------------------------------------------------------------------
#define FPB  272
#define SQHI 0
#define SQLO 17408
#define SKHI 34816
#define SKLO 52224
#define SVHI 69632
#define SVLO 87040
#define SSTAT 104448                 // smax[2][64], ssum[2][64]
#define FL_SMEM (104448 + 1024)
#define MRG_PITCH 132                // fp32 merge pitch (conflict-free)

__global__ __launch_bounds__(256, 2)
void flash_hmma_kernel(const __nv_bfloat16* __restrict__ Qhi,
                       const __nv_bfloat16* __restrict__ Qlo,
                       const __nv_bfloat16* __restrict__ KVhi,
                       const __nv_bfloat16* __restrict__ KVlo,
                       __nv_bfloat16* __restrict__ Ohi,
                       __nv_bfloat16* __restrict__ Olo)
{
    extern __shared__ char dsm[];
    const uint32_t sb = smem_u32(dsm);
    float* smax = (float*)(dsm + SSTAT);          // [2][64]
    float* ssum = (float*)(dsm + SSTAT + 512);    // [2][64]

    const int tid = threadIdx.x, lane = tid & 31, wid = tid >> 5;
    const int wm = wid & 3, wn = wid >> 2;        // 4 x 2 warp grid
    const int lr = lane >> 2, lc2 = (lane & 3) * 2;

    const int bh_ = blockIdx.y;
    const int b = bh_ >> 4, head = bh_ & 15;
    const int qi = gridDim.x - 1 - blockIdx.x;    // heavy blocks first
    const int q0 = qi * 64;
    const size_t baseQ  = ((size_t)b * S_LEN) * QC_W + head * HD;
    const size_t baseKV = ((size_t)b * S_LEN) * KV_W + head * HD;
    const size_t baseO  = ((size_t)b * S_LEN) * D_DIM + head * HD;

    auto load_k = [&](int k0g) {
#pragma unroll
        for (int j = 0; j < 4; j++) {
            int lin = j * 256 + tid;
            int row = lin >> 4, c16 = lin & 15;
            const size_t so = baseKV + (size_t)(k0g + row) * KV_W + c16 * 8;
            const uint32_t doff = row * FPB + c16 * 16;
            cp16(sb + SKHI + doff, KVhi + so);
            cp16(sb + SKLO + doff, KVlo + so);
        }
        CP_COMMIT();
    };
    auto load_v = [&](int k0g) {
#pragma unroll
        for (int j = 0; j < 4; j++) {
            int lin = j * 256 + tid;
            int row = lin >> 4, c16 = lin & 15;
            const size_t so = baseKV + (size_t)(k0g + row) * KV_W + c16 * 8 + 2048;
            const uint32_t doff = row * FPB + c16 * 16;
            cp16(sb + SVHI + doff, KVhi + so);
            cp16(sb + SVLO + doff, KVlo + so);
        }
        CP_COMMIT();
    };

    // Prologue: Q, K0, V0 in flight (3 commit groups).
#pragma unroll
    for (int j = 0; j < 4; j++) {
        int lin = j * 256 + tid;
        int row = lin >> 4, c16 = lin & 15;
        const size_t so = baseQ + (size_t)(q0 + row) * QC_W + c16 * 8;
        const uint32_t doff = row * FPB + c16 * 16;
        cp16(sb + SQHI + doff, Qhi + so);
        cp16(sb + SQLO + doff, Qlo + so);
    }
    CP_COMMIT();
    load_k(0);
    load_v(0);

    float m[2] = {-1e30f, -1e30f}, l[2] = {0.f, 0.f};
    float accO[16][4];
#pragma unroll
    for (int nt = 0; nt < 16; nt++)
#pragma unroll
        for (int e = 0; e < 4; e++) accO[nt][e] = 0.f;

    const float scale = 0.08838834764831845f;
    const int qrow_base = q0 + wm * 16;
    const int srow0 = wm * 16 + lr;               // stats row (h=0)

    for (int kt = 0; kt <= qi; kt++) {
        const int k0g = kt * 64;
        const bool more = (kt < qi);

        // K_kt (and Q) complete; V_kt may still be in flight.
        asm volatile("cp.async.wait_group 1;" ::: "memory");
        __syncthreads();

        // ---- S = Q K^T (warp covers cols [wn*32, wn*32+32)) ----
        float accS[4][4];
#pragma unroll
        for (int n = 0; n < 4; n++)
#pragma unroll
            for (int e = 0; e < 4; e++) accS[n][e] = 0.f;

#pragma unroll
        for (int ks = 0; ks < 8; ks++) {
            const int kk = ks * 16;
            uint32_t qh[4], ql[4];
            const uint32_t qoff = (wm * 16 + (lane & 15)) * FPB
                                  + (kk + ((lane >> 4) << 3)) * 2;
            ldsm4(qh[0], qh[1], qh[2], qh[3], sb + SQHI + qoff);
            ldsm4(ql[0], ql[1], ql[2], ql[3], sb + SQLO + qoff);
#pragma unroll
            for (int np = 0; np < 2; np++) {
                const uint32_t koff =
                    (wn * 32 + np * 16 + (lane & 7) + ((lane >> 4) << 3)) * FPB
                    + (kk + (((lane >> 3) & 1) << 3)) * 2;
                uint32_t bh[4], bl[4];
                ldsm4(bh[0], bh[1], bh[2], bh[3], sb + SKHI + koff);
                ldsm4(bl[0], bl[1], bl[2], bl[3], sb + SKLO + koff);
#pragma unroll
                for (int t = 0; t < 2; t++)
                    mma16816(accS[np * 2 + t], qh, bh[2 * t], bh[2 * t + 1]);
#pragma unroll
                for (int t = 0; t < 2; t++)
                    mma16816(accS[np * 2 + t], qh, bl[2 * t], bl[2 * t + 1]);
#pragma unroll
                for (int t = 0; t < 2; t++)
                    mma16816(accS[np * 2 + t], ql, bh[2 * t], bh[2 * t + 1]);
            }
        }

        // All warps done reading the K tile; prefetch next K.
        __syncthreads();
        if (more) {
            load_k(k0g + 64);
            asm volatile("cp.async.wait_group 1;" ::: "memory");  // V_kt done
        } else {
            asm volatile("cp.async.wait_group 0;" ::: "memory");
        }
        __syncthreads();

        // ---- mask + scale ----
        const bool diag = (kt == qi);
#pragma unroll
        for (int n = 0; n < 4; n++) {
#pragma unroll
            for (int e = 0; e < 4; e++) {
                float v = accS[n][e] * scale;
                if (diag) {
                    int row = qrow_base + lr + 8 * (e >> 1);
                    int col = k0g + wn * 32 + n * 8 + lc2 + (e & 1);
                    if (col > row) v = -1e30f;
                }
                accS[n][e] = v;
            }
        }

        // ---- online softmax with cross-warp (wn pair) stats ----
        float mt[2];
#pragma unroll
        for (int h = 0; h < 2; h++) {
            float v = -1e30f;
#pragma unroll
            for (int n = 0; n < 4; n++)
                v = fmaxf(v, fmaxf(accS[n][2 * h], accS[n][2 * h + 1]));
            v = fmaxf(v, __shfl_xor_sync(0xffffffffu, v, 1));
            v = fmaxf(v, __shfl_xor_sync(0xffffffffu, v, 2));
            mt[h] = v;
        }
        if ((lane & 3) == 0) {
            smax[wn * 64 + srow0]     = mt[0];
            smax[wn * 64 + srow0 + 8] = mt[1];
        }
        __syncthreads();

        float alpha[2], lt[2];
#pragma unroll
        for (int h = 0; h < 2; h++) {
            float other = smax[(1 - wn) * 64 + srow0 + 8 * h];
            float mn = fmaxf(m[h], fmaxf(mt[h], other));
            alpha[h] = __expf(m[h] - mn);
            m[h] = mn;
            float s = 0.f;
#pragma unroll
            for (int n = 0; n < 4; n++) {
                float p0 = __expf(accS[n][2 * h] - mn);
                float p1 = __expf(accS[n][2 * h + 1] - mn);
                accS[n][2 * h] = p0;
                accS[n][2 * h + 1] = p1;
                s += p0 + p1;
            }
            s += __shfl_xor_sync(0xffffffffu, s, 1);
            s += __shfl_xor_sync(0xffffffffu, s, 2);
            lt[h] = s;
        }
        if ((lane & 3) == 0) {
            ssum[wn * 64 + srow0]     = lt[0];
            ssum[wn * 64 + srow0 + 8] = lt[1];
        }
        __syncthreads();
#pragma unroll
        for (int h = 0; h < 2; h++) {
            float other = ssum[(1 - wn) * 64 + srow0 + 8 * h];
            l[h] = l[h] * alpha[h] + (lt[h] + other);
#pragma unroll
            for (int nt = 0; nt < 16; nt++) {
                accO[nt][2 * h] *= alpha[h];
                accO[nt][2 * h + 1] *= alpha[h];
            }
        }

        // ---- O += P V (warp covers k-rows [wn*32, wn*32+32)) ----
#pragma unroll
        for (int t = 0; t < 2; t++) {
            uint32_t phi[4], plo[4];
#pragma unroll
            for (int half = 0; half < 2; half++) {
                float* s = accS[2 * t + half];
#pragma unroll
                for (int rh = 0; rh < 2; rh++) {
                    float v0 = s[2 * rh], v1 = s[2 * rh + 1];
                    __nv_bfloat16 h0 = __float2bfloat16(v0);
                    __nv_bfloat16 h1 = __float2bfloat16(v1);
                    phi[half * 2 + rh] = packbf2(h0, h1);
                    plo[half * 2 + rh] = packbf2(
                        __float2bfloat16(v0 - __bfloat162float(h0)),
                        __float2bfloat16(v1 - __bfloat162float(h1)));
                }
            }
            const int kk = wn * 32 + t * 16;
#pragma unroll
            for (int np = 0; np < 8; np++) {
                const uint32_t voff = (kk + (lane & 15)) * FPB
                                      + (np * 16 + ((lane >> 4) << 3)) * 2;
                uint32_t vh[4], vl[4];
                ldsm4t(vh[0], vh[1], vh[2], vh[3], sb + SVHI + voff);
                ldsm4t(vl[0], vl[1], vl[2], vl[3], sb + SVLO + voff);
#pragma unroll
                for (int u = 0; u < 2; u++)
                    mma16816(accO[np * 2 + u], phi, vh[2 * u], vh[2 * u + 1]);
#pragma unroll
                for (int u = 0; u < 2; u++)
                    mma16816(accO[np * 2 + u], phi, vl[2 * u], vl[2 * u + 1]);
#pragma unroll
                for (int u = 0; u < 2; u++)
                    mma16816(accO[np * 2 + u], plo, vh[2 * u], vh[2 * u + 1]);
            }
        }

        // All warps done reading the V tile; prefetch next V.
        if (more) {
            __syncthreads();
            load_v(k0g + 64);
        }
    }

    // ---- merge partial O across the wn pair (K smem region is free) ----
    float* mrg = (float*)(dsm + SKHI);
    __syncthreads();
    if (wn == 1) {
#pragma unroll
        for (int nt = 0; nt < 16; nt++) {
#pragma unroll
            for (int h = 0; h < 2; h++) {
                const int row = wm * 16 + lr + 8 * h;
                const int col = nt * 8 + lc2;
                mrg[row * MRG_PITCH + col]     = accO[nt][2 * h];
                mrg[row * MRG_PITCH + col + 1] = accO[nt][2 * h + 1];
            }
        }
    }
    __syncthreads();
    if (wn == 0) {
        const float inv0 = 1.0f / l[0], inv1 = 1.0f / l[1];
#pragma unroll
        for (int nt = 0; nt < 16; nt++) {
#pragma unroll
            for (int h = 0; h < 2; h++) {
                const float inv = h ? inv1 : inv0;
                const int row = wm * 16 + lr + 8 * h;
                const int col = nt * 8 + lc2;
                float v0 = (accO[nt][2 * h]     + mrg[row * MRG_PITCH + col])     * inv;
                float v1 = (accO[nt][2 * h + 1] + mrg[row * MRG_PITCH + col + 1]) * inv;
                __nv_bfloat16 h0 = __float2bfloat16(v0);
                __nv_bfloat16 h1 = __float2bfloat16(v1);
                const size_t o = baseO
                    + (size_t)(qrow_base + lr + 8 * h) * D_DIM + nt * 8 + lc2;
                *(uint32_t*)(Ohi + o) = packbf2(h0, h1);
                *(uint32_t*)(Olo + o) = packbf2(
                    __float2bfloat16(v0 - __bfloat162float(h0)),
                    __float2bfloat16(v1 - __bfloat162float(h1)));
            }
        }
    }
}

// ---------------------------------------------------------------------------
// Launch
// Inputs: x, freqs, mask(unused: exactly causal), Wq, Wdown, Wkup, Wvup, Wo
// ---------------------------------------------------------------------------
extern "C" void kernel_launch(void* const* d_in, const int* in_sizes, int n_in,
                              void* d_out, int out_size)
{
    const float* x     = (const float*)d_in[0];
    const float* freqs = (const float*)d_in[1];
    const float* Wq    = (const float*)d_in[3];
    const float* Wdn   = (const float*)d_in[4];
    const float* Wku   = (const float*)d_in[5];
    const float* Wvu   = (const float*)d_in[6];
    const float* Wo    = (const float*)d_in[7];
    float* out = (float*)d_out;

    __nv_bfloat16 *xhi, *xlo, *wthi, *wtlo;
    __nv_bfloat16 *qchi, *qclo, *kvhi, *kvlo, *ohi, *olo;
    float2* cstab;
    cudaGetSymbolAddress((void**)&xhi, g_xhi);
    cudaGetSymbolAddress((void**)&xlo, g_xlo);
    cudaGetSymbolAddress((void**)&qchi, g_qchi);
    cudaGetSymbolAddress((void**)&qclo, g_qclo);
    cudaGetSymbolAddress((void**)&kvhi, g_kvhi);
    cudaGetSymbolAddress((void**)&kvlo, g_kvlo);
    cudaGetSymbolAddress((void**)&ohi, g_ohi);
    cudaGetSymbolAddress((void**)&olo, g_olo);
    cudaGetSymbolAddress((void**)&wthi, g_wthi);
    cudaGetSymbolAddress((void**)&wtlo, g_wtlo);
    cudaGetSymbolAddress((void**)&cstab, g_cs);

    cudaFuncSetAttribute(gemm_hilo_kernel,
                         cudaFuncAttributeMaxDynamicSharedMemorySize, GK_SMEM_DYN);
    cudaFuncSetAttribute(flash_hmma_kernel,
                         cudaFuncAttributeMaxDynamicSharedMemorySize, FL_SMEM);

    dim3 tb(32, 8);
    const int nx = ROWS_TOT * D_DIM;
    const int ncs = S_LEN * (HD / 2);

    // Prep (bandwidth-bound)
    transpose_hilo_kernel<<<dim3(64, 64), tb>>>(Wq,  wthi + OFF_WQ,  wtlo + OFF_WQ,  2048, 2048);
    transpose_hilo_kernel<<<dim3(16, 64), tb>>>(Wdn, wthi + OFF_WDN, wtlo + OFF_WDN, 2048, 512);
    convert_hilo_kernel<<<nx / 256, 256>>>(x, xhi, xlo, nx);
    rope_table_kernel<<<(ncs + 255) / 256, 256>>>(freqs, cstab);
    transpose_hilo_kernel<<<dim3(64, 16), tb>>>(Wku, wthi + OFF_WKU, wtlo + OFF_WKU, 512, 2048);

    // Merged Q|c projection: x @ [Wq|Wdown], N=2560, RoPE on cols < 2048.
    gemm_hilo_kernel<<<GK_GRID, 256, GK_SMEM_DYN>>>(
        xhi, xlo, wthi + OFF_WQ, wtlo + OFF_WQ,
        nullptr, qchi, qclo, cstab, 2048,
        ROWS_TOT, QC_W, D_DIM, D_DIM, QC_W);

    transpose_hilo_kernel<<<dim3(64, 16), tb>>>(Wvu, wthi + OFF_WVU, wtlo + OFF_WVU, 512, 2048);
    transpose_hilo_kernel<<<dim3(64, 64), tb>>>(Wo,  wthi + OFF_WO,  wtlo + OFF_WO,  2048, 2048);

    // Merged K|V up-projection: c @ [Wkup|Wvup], N=4096, RoPE on cols < 2048.
    gemm_hilo_kernel<<<GK_GRID, 256, GK_SMEM_DYN>>>(
        qchi + 2048, qclo + 2048, wthi + OFF_WKU, wtlo + OFF_WKU,
        nullptr, kvhi, kvlo, cstab, 2048,
        ROWS_TOT, KV_W, LAT, QC_W, KV_W);

    // Flash attention v2 (causal, HMMA hi/lo, 8 warps, N-split softmax)
    flash_hmma_kernel<<<dim3(S_LEN / 64, BATCH * NH), 256, FL_SMEM>>>(
        qchi, qclo, kvhi, kvlo, ohi, olo);

    // Output projection (fp32 out)
    gemm_hilo_kernel<<<GK_GRID, 256, GK_SMEM_DYN>>>(
        ohi, olo, wthi + OFF_WO, wtlo + OFF_WO,
        out, nullptr, nullptr, nullptr, 0,
        ROWS_TOT, D_DIM, D_DIM, D_DIM, D_DIM);
}

// round 14
// speedup vs baseline: 1.0443x; 1.0443x over previous
#include <cuda_runtime.h>
#include <cuda_bf16.h>
#include <cstdint>
#include <math.h>

// Problem constants
#define BATCH   2
#define S_LEN   2048
#define D_DIM   2048
#define NH      16
#define HD      128
#define LAT     512
#define ROWS_TOT (BATCH * S_LEN)   // 4096
#define KV_W    4096               // merged K|V row width
#define QC_W    2560               // merged Q|c row width (2048 Q + 512 c)

// ---------------------------------------------------------------------------
// Scratch (__device__ globals; allocation-free rule)
// ---------------------------------------------------------------------------
__device__ __nv_bfloat16 g_xhi[ROWS_TOT * D_DIM];
__device__ __nv_bfloat16 g_xlo[ROWS_TOT * D_DIM];
__device__ __nv_bfloat16 g_qchi[ROWS_TOT * QC_W];   // [0,2048)=Q(roped), [2048,2560)=c
__device__ __nv_bfloat16 g_qclo[ROWS_TOT * QC_W];
__device__ __nv_bfloat16 g_kvhi[ROWS_TOT * KV_W];   // [0,2048)=K(roped), [2048,4096)=V
__device__ __nv_bfloat16 g_kvlo[ROWS_TOT * KV_W];
__device__ __nv_bfloat16 g_ohi[ROWS_TOT * D_DIM];
__device__ __nv_bfloat16 g_olo[ROWS_TOT * D_DIM];
__device__ float2 g_cs[S_LEN * (HD / 2)];           // RoPE cos/sin table

// Transposed-weight pool ([N,K] K-major bf16), hi and lo parts.
#define OFF_WQ  0
#define OFF_WDN 4194304
#define OFF_WKU 5242880
#define OFF_WVU 6291456
#define OFF_WO  7340032
#define WT_TOTAL 11534336
__device__ __nv_bfloat16 g_wthi[WT_TOTAL];
__device__ __nv_bfloat16 g_wtlo[WT_TOTAL];

// ---------------------------------------------------------------------------
// PTX helpers (sm_80+ features only — harness targets plain sm_103)
// ---------------------------------------------------------------------------
__device__ __forceinline__ uint32_t smem_u32(const void* p) {
    uint32_t a;
    asm("{ .reg .u64 t; cvta.to.shared.u64 t, %1; cvt.u32.u64 %0, t; }"
        : "=r"(a) : "l"(p));
    return a;
}
__device__ __forceinline__ void cp16(uint32_t dst, const void* src) {
    asm volatile("cp.async.cg.shared.global [%0], [%1], 16;" :: "r"(dst), "l"(src));
}
#define CP_COMMIT() asm volatile("cp.async.commit_group;" ::: "memory")

__device__ __forceinline__ void ldsm4(uint32_t& r0, uint32_t& r1,
                                      uint32_t& r2, uint32_t& r3, uint32_t a) {
    asm volatile("ldmatrix.sync.aligned.m8n8.x4.shared.b16 {%0,%1,%2,%3}, [%4];"
                 : "=r"(r0), "=r"(r1), "=r"(r2), "=r"(r3) : "r"(a));
}
__device__ __forceinline__ void ldsm4t(uint32_t& r0, uint32_t& r1,
                                       uint32_t& r2, uint32_t& r3, uint32_t a) {
    asm volatile("ldmatrix.sync.aligned.m8n8.x4.trans.shared.b16 {%0,%1,%2,%3}, [%4];"
                 : "=r"(r0), "=r"(r1), "=r"(r2), "=r"(r3) : "r"(a));
}
// Non-volatile: pure register op; lets ptxas interleave MMAs to break
// accumulator RAW chains.
__device__ __forceinline__ void mma16816(float* d, const uint32_t* a,
                                         uint32_t b0, uint32_t b1) {
    asm("mma.sync.aligned.m16n8k16.row.col.f32.bf16.bf16.f32 "
        "{%0,%1,%2,%3}, {%4,%5,%6,%7}, {%8,%9}, {%0,%1,%2,%3};"
        : "+f"(d[0]), "+f"(d[1]), "+f"(d[2]), "+f"(d[3])
        : "r"(a[0]), "r"(a[1]), "r"(a[2]), "r"(a[3]), "r"(b0), "r"(b1));
}
__device__ __forceinline__ uint32_t packbf2(__nv_bfloat16 x, __nv_bfloat16 y) {
    __nv_bfloat162 t(x, y);
    return *(uint32_t*)&t;
}
__device__ __forceinline__ float ex2(float x) {
    float r;
    asm("ex2.approx.f32 %0, %1;" : "=f"(r) : "f"(x));
    return r;
}

// XOR chunk swizzle for 64B-pitch rows (4 x 16B chunks per row).
__device__ __forceinline__ uint32_t swz64(int row, int chunk) {
    return (uint32_t)(row * 64 + ((chunk ^ ((row >> 1) & 3)) << 4));
}

// ---------------------------------------------------------------------------
// HMMA bf16 hi/lo GEMM (persistent). Round-12 mainloop + cross-tile stage
// rotation: the next tile's stage-0/1 cp.async issue BEFORE the epilogue,
// hiding the per-tile load lead-in under epilogue stores.
// ---------------------------------------------------------------------------
#define ST_AHI  0
#define ST_ALO  8192
#define ST_BHI  16384
#define ST_BLO  24576
#define STAGE_B 32768
#define GK_SMEM_DYN (3 * STAGE_B)   // 96 KB
#define GK_GRID 296                 // 2 CTAs x 148 SMs

__global__ __launch_bounds__(256, 2)
void gemm_hilo_kernel(const __nv_bfloat16* __restrict__ Ahi,
                      const __nv_bfloat16* __restrict__ Alo,
                      const __nv_bfloat16* __restrict__ Bhi,
                      const __nv_bfloat16* __restrict__ Blo,
                      float* __restrict__ Cout,
                      __nv_bfloat16* __restrict__ Chi,
                      __nv_bfloat16* __restrict__ Clo,
                      const float2* __restrict__ cstab,
                      int rope_cols,
                      int M, int N, int K, int lda, int ldc)
{
    extern __shared__ char dsm[];
    const uint32_t sbase = smem_u32(dsm);
    const int tid = threadIdx.x, lane = tid & 31, wid = tid >> 5;
    const int wm = wid & 3, wn = wid >> 2;           // 4 x 2 warp grid
    const int lrow = tid >> 1;
    const int lc0  = (tid & 1) * 2;
    const int lr = lane >> 2, lc = (lane & 3) * 2;
    const int nk = K >> 5;
    const int ntx = N >> 7;
    const int ntiles = (M >> 7) * ntx;

    auto load_stage = [&](int buf, int kc,
                          const __nv_bfloat16* Ah, const __nv_bfloat16* Al,
                          const __nv_bfloat16* Bh, const __nv_bfloat16* Bl) {
        const uint32_t st = sbase + buf * STAGE_B;
        const size_t koff = (size_t)kc * 32;
#pragma unroll
        for (int t = 0; t < 2; t++) {
            const int c = lc0 + t;
            const uint32_t doff = swz64(lrow, c);
            cp16(st + ST_AHI + doff, Ah + (size_t)lrow * lda + koff + c * 8);
            cp16(st + ST_ALO + doff, Al + (size_t)lrow * lda + koff + c * 8);
            cp16(st + ST_BHI + doff, Bh + (size_t)lrow * K + koff + c * 8);
            cp16(st + ST_BLO + doff, Bl + (size_t)lrow * K + koff + c * 8);
        }
        CP_COMMIT();
    };

    int tile = blockIdx.x;
    bool valid = tile < ntiles;
    int buf = 0;
    int m0 = 0, n0 = 0;
    const __nv_bfloat16 *cAh = Ahi, *cAl = Alo, *cBh = Bhi, *cBl = Blo;
    if (valid) {
        const int tyi = tile / ntx, txi = tile - tyi * ntx;
        m0 = tyi * 128; n0 = txi * 128;
        cAh = Ahi + (size_t)m0 * lda;
        cAl = Alo + (size_t)m0 * lda;
        cBh = Bhi + (size_t)n0 * K;
        cBl = Blo + (size_t)n0 * K;
        load_stage(0, 0, cAh, cAl, cBh, cBl);
        load_stage(1, 1, cAh, cAl, cBh, cBl);
    }

    while (valid) {
        float acc[2][8][4];
#pragma unroll
        for (int mt = 0; mt < 2; mt++)
#pragma unroll
            for (int nt = 0; nt < 8; nt++)
#pragma unroll
                for (int r = 0; r < 4; r++) acc[mt][nt][r] = 0.f;

        for (int k = 0; k < nk; k++) {
            if (k + 1 < nk)
                asm volatile("cp.async.wait_group 1;" ::: "memory");
            else
                asm volatile("cp.async.wait_group 0;" ::: "memory");
            __syncthreads();

            if (k + 2 < nk)
                load_stage((buf + k + 2) % 3, k + 2, cAh, cAl, cBh, cBl);

            const uint32_t st = sbase + ((buf + k) % 3) * STAGE_B;
#pragma unroll
            for (int ks = 0; ks < 2; ks++) {
                uint32_t ah[2][4], al[2][4];
#pragma unroll
                for (int mt = 0; mt < 2; mt++) {
                    const int row = wm * 32 + mt * 16 + (lane & 15);
                    const uint32_t off = swz64(row, ks * 2 + (lane >> 4));
                    ldsm4(ah[mt][0], ah[mt][1], ah[mt][2], ah[mt][3],
                          st + ST_AHI + off);
                    ldsm4(al[mt][0], al[mt][1], al[mt][2], al[mt][3],
                          st + ST_ALO + off);
                }
#pragma unroll
                for (int bp = 0; bp < 4; bp++) {
                    const int rn = wn * 64 + bp * 16 + ((lane >> 4) << 3) + (lane & 7);
                    const uint32_t off = swz64(rn, ks * 2 + ((lane >> 3) & 1));
                    uint32_t bh[4], bl[4];
                    ldsm4(bh[0], bh[1], bh[2], bh[3], st + ST_BHI + off);
                    ldsm4(bl[0], bl[1], bl[2], bl[3], st + ST_BLO + off);
#pragma unroll
                    for (int mt = 0; mt < 2; mt++)
#pragma unroll
                        for (int h = 0; h < 2; h++)
                            mma16816(acc[mt][2 * bp + h], ah[mt], bh[2 * h], bh[2 * h + 1]);
#pragma unroll
                    for (int mt = 0; mt < 2; mt++)
#pragma unroll
                        for (int h = 0; h < 2; h++)
                            mma16816(acc[mt][2 * bp + h], ah[mt], bl[2 * h], bl[2 * h + 1]);
#pragma unroll
                    for (int mt = 0; mt < 2; mt++)
#pragma unroll
                        for (int h = 0; h < 2; h++)
                            mma16816(acc[mt][2 * bp + h], al[mt], bh[2 * h], bh[2 * h + 1]);
                }
            }
        }

        buf = (buf + nk) % 3;
        const int ntile = tile + gridDim.x;
        const bool nvalid = ntile < ntiles;
        int nm0 = 0, nn0 = 0;
        const __nv_bfloat16 *nAh = cAh, *nAl = cAl, *nBh = cBh, *nBl = cBl;

        __syncthreads();   // all warps finished reading smem of this tile
        if (nvalid) {
            const int tyi = ntile / ntx, txi = ntile - tyi * ntx;
            nm0 = tyi * 128; nn0 = txi * 128;
            nAh = Ahi + (size_t)nm0 * lda;
            nAl = Alo + (size_t)nm0 * lda;
            nBh = Bhi + (size_t)nn0 * K;
            nBl = Blo + (size_t)nn0 * K;
            // Issue next tile's stage 0/1 now; they complete under the
            // epilogue below.
            load_stage(buf, 0, nAh, nAl, nBh, nBl);
            load_stage((buf + 1) % 3, 1, nAh, nAl, nBh, nBl);
        }

        // ---- epilogue for current tile ----
        const int rbase = m0 + wm * 32, cbase = n0 + wn * 64;
        if (Cout) {
#pragma unroll
            for (int mt = 0; mt < 2; mt++) {
#pragma unroll
                for (int nt = 0; nt < 8; nt++) {
                    float* d = acc[mt][nt];
                    const size_t r0 = (size_t)(rbase + mt * 16 + lr) * ldc
                                      + cbase + nt * 8 + lc;
                    *(float2*)(Cout + r0)           = make_float2(d[0], d[1]);
                    *(float2*)(Cout + r0 + 8 * ldc) = make_float2(d[2], d[3]);
                }
            }
        } else {
            const bool do_rope = (cstab != nullptr) && (cbase < rope_cols);
#pragma unroll
            for (int mt = 0; mt < 2; mt++) {
#pragma unroll
                for (int nt = 0; nt < 8; nt++) {
                    float* d = acc[mt][nt];
#pragma unroll
                    for (int half = 0; half < 2; half++) {
                        const int row = rbase + mt * 16 + lr + half * 8;
                        const int col = cbase + nt * 8 + lc;
                        float v0 = d[half * 2], v1 = d[half * 2 + 1];
                        if (do_rope) {
                            const int s = row & (S_LEN - 1);
                            const int p = (col & (HD - 1)) >> 1;
                            float2 cs = __ldg(cstab + s * (HD / 2) + p);
                            float r0 = v0 * cs.x - v1 * cs.y;
                            float r1 = v0 * cs.y + v1 * cs.x;
                            v0 = r0; v1 = r1;
                        }
                        __nv_bfloat16 h0 = __float2bfloat16(v0);
                        __nv_bfloat16 h1 = __float2bfloat16(v1);
                        const size_t o = (size_t)row * ldc + col;
                        *(uint32_t*)(Chi + o) = packbf2(h0, h1);
                        *(uint32_t*)(Clo + o) = packbf2(
                            __float2bfloat16(v0 - __bfloat162float(h0)),
                            __float2bfloat16(v1 - __bfloat162float(h1)));
                    }
                }
            }
        }

        tile = ntile;
        valid = nvalid;
        m0 = nm0; n0 = nn0;
        cAh = nAh; cAl = nAl; cBh = nBh; cBl = nBl;
    }
}

// ---------------------------------------------------------------------------
// Prep kernels
// ---------------------------------------------------------------------------
__global__ void convert_hilo_kernel(const float* __restrict__ in,
                                    __nv_bfloat16* __restrict__ hi,
                                    __nv_bfloat16* __restrict__ lo, int n)
{
    int i = blockIdx.x * blockDim.x + threadIdx.x;
    if (i >= n) return;
    float v = in[i];
    __nv_bfloat16 h = __float2bfloat16(v);
    hi[i] = h;
    lo[i] = __float2bfloat16(v - __bfloat162float(h));
}

__global__ void rope_table_kernel(const float* __restrict__ freqs,
                                  float2* __restrict__ cstab)
{
    int i = blockIdx.x * blockDim.x + threadIdx.x;
    if (i >= S_LEN * (HD / 2)) return;
    float f = freqs[i];
    float sn, cs;
    sincosf(f, &sn, &cs);
    cstab[i] = make_float2(cs, sn);
}

__global__ void transpose_hilo_kernel(const float* __restrict__ W,
                                      __nv_bfloat16* __restrict__ hi,
                                      __nv_bfloat16* __restrict__ lo,
                                      int Kd, int Nd)
{
    __shared__ float t[32][33];
    const int tx = threadIdx.x, ty = threadIdx.y;
    const int k0 = blockIdx.y * 32, n0 = blockIdx.x * 32;
#pragma unroll
    for (int i = 0; i < 4; i++)
        t[ty + i * 8][tx] = W[(size_t)(k0 + ty + i * 8) * Nd + n0 + tx];
    __syncthreads();
#pragma unroll
    for (int i = 0; i < 4; i++) {
        float v = t[tx][ty + i * 8];
        __nv_bfloat16 h = __float2bfloat16(v);
        size_t o = (size_t)(n0 + ty + i * 8) * Kd + k0 + tx;
        hi[o] = h;
        lo[o] = __float2bfloat16(v - __bfloat162float(h));
    }
}

// ---------------------------------------------------------------------------
// HMMA causal flash attention (round-12 design, known-best), bf16 hi/lo,
// log2-domain softmax (scale folds in log2(e); raw ex2.approx).
// BR=BC=64, 128 threads (4 warps x 16 q-rows), staggered K/V cp.async.
// ---------------------------------------------------------------------------
#define FPB  272
#define SQHI 0
#define SQLO 17408
#define SKHI 34816
#define SKLO 52224
#define SVHI 69632
#define SVLO 87040
#define FL_SMEM 104448

__global__ __launch_bounds__(128)
void flash_hmma_kernel(const __nv_bfloat16* __restrict__ Qhi,
                       const __nv_bfloat16* __restrict__ Qlo,
                       const __nv_bfloat16* __restrict__ KVhi,
                       const __nv_bfloat16* __restrict__ KVlo,
                       __nv_bfloat16* __restrict__ Ohi,
                       __nv_bfloat16* __restrict__ Olo)
{
    extern __shared__ char dsm[];
    const uint32_t sb = smem_u32(dsm);

    const int tid = threadIdx.x, lane = tid & 31, wm = tid >> 5;
    const int lr = lane >> 2, lc2 = (lane & 3) * 2;

    const int bh_ = blockIdx.y;
    const int b = bh_ >> 4, head = bh_ & 15;
    const int qi = gridDim.x - 1 - blockIdx.x;       // heavy blocks first
    const int q0 = qi * 64;
    const size_t baseQ  = ((size_t)b * S_LEN) * QC_W + head * HD;
    const size_t baseKV = ((size_t)b * S_LEN) * KV_W + head * HD;
    const size_t baseO  = ((size_t)b * S_LEN) * D_DIM + head * HD;

    auto load_k = [&](int k0g) {
#pragma unroll
        for (int j = 0; j < 8; j++) {
            int lin = j * 128 + tid;
            int row = lin >> 4, c16 = lin & 15;
            const size_t so = baseKV + (size_t)(k0g + row) * KV_W + c16 * 8;
            const uint32_t doff = row * FPB + c16 * 16;
            cp16(sb + SKHI + doff, KVhi + so);
            cp16(sb + SKLO + doff, KVlo + so);
        }
        CP_COMMIT();
    };
    auto load_v = [&](int k0g) {
#pragma unroll
        for (int j = 0; j < 8; j++) {
            int lin = j * 128 + tid;
            int row = lin >> 4, c16 = lin & 15;
            const size_t so = baseKV + (size_t)(k0g + row) * KV_W + c16 * 8 + 2048;
            const uint32_t doff = row * FPB + c16 * 16;
            cp16(sb + SVHI + doff, KVhi + so);
            cp16(sb + SVLO + doff, KVlo + so);
        }
        CP_COMMIT();
    };

    // Prologue: Q, K0, V0 in flight (3 commit groups).
#pragma unroll
    for (int j = 0; j < 8; j++) {
        int lin = j * 128 + tid;
        int row = lin >> 4, c16 = lin & 15;
        const size_t so = baseQ + (size_t)(q0 + row) * QC_W + c16 * 8;
        const uint32_t doff = row * FPB + c16 * 16;
        cp16(sb + SQHI + doff, Qhi + so);
        cp16(sb + SQLO + doff, Qlo + so);
    }
    CP_COMMIT();
    load_k(0);
    load_v(0);

    float m[2] = {-1e30f, -1e30f}, l[2] = {0.f, 0.f};
    float accO[16][4];
#pragma unroll
    for (int nt = 0; nt < 16; nt++)
#pragma unroll
        for (int e = 0; e < 4; e++) accO[nt][e] = 0.f;

    // scale * log2(e): softmax carried in the log2 domain (monotonic; math
    // identical to nat-log softmax, one FMUL per exp cheaper via raw ex2).
    const float scale2 = 0.08838834764831845f * 1.4426950408889634f;
    const int qrow_base = q0 + wm * 16;

    for (int kt = 0; kt <= qi; kt++) {
        const int k0g = kt * 64;
        const bool more = (kt < qi);

        // K_kt (and Q) complete; V_kt may still be in flight.
        asm volatile("cp.async.wait_group 1;" ::: "memory");
        __syncthreads();

        // ---- S = Q K^T ----
        float accS[8][4];
#pragma unroll
        for (int n = 0; n < 8; n++)
#pragma unroll
            for (int e = 0; e < 4; e++) accS[n][e] = 0.f;

#pragma unroll
        for (int ks = 0; ks < 8; ks++) {
            const int kk = ks * 16;
            uint32_t qh[4], ql[4];
            const uint32_t qoff = (wm * 16 + (lane & 15)) * FPB
                                  + (kk + ((lane >> 4) << 3)) * 2;
            ldsm4(qh[0], qh[1], qh[2], qh[3], sb + SQHI + qoff);
            ldsm4(ql[0], ql[1], ql[2], ql[3], sb + SQLO + qoff);
#pragma unroll
            for (int np = 0; np < 4; np++) {
                const uint32_t koff =
                    (np * 16 + (lane & 7) + ((lane >> 4) << 3)) * FPB
                    + (kk + (((lane >> 3) & 1) << 3)) * 2;
                uint32_t bh[4], bl[4];
                ldsm4(bh[0], bh[1], bh[2], bh[3], sb + SKHI + koff);
                ldsm4(bl[0], bl[1], bl[2], bl[3], sb + SKLO + koff);
#pragma unroll
                for (int t = 0; t < 2; t++)
                    mma16816(accS[np * 2 + t], qh, bh[2 * t], bh[2 * t + 1]);
#pragma unroll
                for (int t = 0; t < 2; t++)
                    mma16816(accS[np * 2 + t], qh, bl[2 * t], bl[2 * t + 1]);
#pragma unroll
                for (int t = 0; t < 2; t++)
                    mma16816(accS[np * 2 + t], ql, bh[2 * t], bh[2 * t + 1]);
            }
        }

        // All warps done reading the K tile; prefetch next K.
        __syncthreads();
        if (more) {
            load_k(k0g + 64);
            asm volatile("cp.async.wait_group 1;" ::: "memory");  // V_kt done
        } else {
            asm volatile("cp.async.wait_group 0;" ::: "memory");
        }
        __syncthreads();

        // ---- mask + log2-domain online softmax ----
        const bool diag = (kt == qi);
#pragma unroll
        for (int n = 0; n < 8; n++) {
#pragma unroll
            for (int e = 0; e < 4; e++) {
                float v = accS[n][e] * scale2;
                if (diag) {
                    int row = qrow_base + lr + 8 * (e >> 1);
                    int col = k0g + n * 8 + lc2 + (e & 1);
                    if (col > row) v = -1e30f;
                }
                accS[n][e] = v;
            }
        }

#pragma unroll
        for (int h = 0; h < 2; h++) {
            float mt = -1e30f;
#pragma unroll
            for (int n = 0; n < 8; n++)
                mt = fmaxf(mt, fmaxf(accS[n][2 * h], accS[n][2 * h + 1]));
            mt = fmaxf(mt, __shfl_xor_sync(0xffffffffu, mt, 1));
            mt = fmaxf(mt, __shfl_xor_sync(0xffffffffu, mt, 2));
            float mn = fmaxf(m[h], mt);
            float alpha = ex2(m[h] - mn);
            m[h] = mn;
            float lt = 0.f;
#pragma unroll
            for (int n = 0; n < 8; n++) {
                float p0 = ex2(accS[n][2 * h] - mn);
                float p1 = ex2(accS[n][2 * h + 1] - mn);
                accS[n][2 * h] = p0;
                accS[n][2 * h + 1] = p1;
                lt += p0 + p1;
            }
            lt += __shfl_xor_sync(0xffffffffu, lt, 1);
            lt += __shfl_xor_sync(0xffffffffu, lt, 2);
            l[h] = l[h] * alpha + lt;
#pragma unroll
            for (int nt = 0; nt < 16; nt++) {
                accO[nt][2 * h] *= alpha;
                accO[nt][2 * h + 1] *= alpha;
            }
        }

        // ---- O += P V ----
#pragma unroll
        for (int t = 0; t < 4; t++) {
            uint32_t phi[4], plo[4];
#pragma unroll
            for (int half = 0; half < 2; half++) {
                float* s = accS[2 * t + half];
#pragma unroll
                for (int rh = 0; rh < 2; rh++) {
                    float v0 = s[2 * rh], v1 = s[2 * rh + 1];
                    __nv_bfloat16 h0 = __float2bfloat16(v0);
                    __nv_bfloat16 h1 = __float2bfloat16(v1);
                    phi[half * 2 + rh] = packbf2(h0, h1);
                    plo[half * 2 + rh] = packbf2(
                        __float2bfloat16(v0 - __bfloat162float(h0)),
                        __float2bfloat16(v1 - __bfloat162float(h1)));
                }
            }
            const int kk = t * 16;
#pragma unroll
            for (int np = 0; np < 8; np++) {
                const uint32_t voff = (kk + (lane & 15)) * FPB
                                      + (np * 16 + ((lane >> 4) << 3)) * 2;
                uint32_t vh[4], vl[4];
                ldsm4t(vh[0], vh[1], vh[2], vh[3], sb + SVHI + voff);
                ldsm4t(vl[0], vl[1], vl[2], vl[3], sb + SVLO + voff);
#pragma unroll
                for (int u = 0; u < 2; u++)
                    mma16816(accO[np * 2 + u], phi, vh[2 * u], vh[2 * u + 1]);
#pragma unroll
                for (int u = 0; u < 2; u++)
                    mma16816(accO[np * 2 + u], phi, vl[2 * u], vl[2 * u + 1]);
#pragma unroll
                for (int u = 0; u < 2; u++)
                    mma16816(accO[np * 2 + u], plo, vh[2 * u], vh[2 * u + 1]);
            }
        }

        // All warps done reading the V tile; prefetch next V.
        if (more) {
            __syncthreads();
            load_v(k0g + 64);
        }
    }

    const float inv0 = 1.0f / l[0], inv1 = 1.0f / l[1];
#pragma unroll
    for (int nt = 0; nt < 16; nt++) {
#pragma unroll
        for (int h = 0; h < 2; h++) {
            float inv = h ? inv1 : inv0;
            float v0 = accO[nt][2 * h] * inv;
            float v1 = accO[nt][2 * h + 1] * inv;
            __nv_bfloat16 h0 = __float2bfloat16(v0);
            __nv_bfloat16 h1 = __float2bfloat16(v1);
            const size_t o = baseO
                + (size_t)(qrow_base + lr + 8 * h) * D_DIM + nt * 8 + lc2;
            *(uint32_t*)(Ohi + o) = packbf2(h0, h1);
            *(uint32_t*)(Olo + o) = packbf2(
                __float2bfloat16(v0 - __bfloat162float(h0)),
                __float2bfloat16(v1 - __bfloat162float(h1)));
        }
    }
}

// ---------------------------------------------------------------------------
// Launch
// Inputs: x, freqs, mask(unused: exactly causal), Wq, Wdown, Wkup, Wvup, Wo
// ---------------------------------------------------------------------------
extern "C" void kernel_launch(void* const* d_in, const int* in_sizes, int n_in,
                              void* d_out, int out_size)
{
    const float* x     = (const float*)d_in[0];
    const float* freqs = (const float*)d_in[1];
    const float* Wq    = (const float*)d_in[3];
    const float* Wdn   = (const float*)d_in[4];
    const float* Wku   = (const float*)d_in[5];
    const float* Wvu   = (const float*)d_in[6];
    const float* Wo    = (const float*)d_in[7];
    float* out = (float*)d_out;

    __nv_bfloat16 *xhi, *xlo, *wthi, *wtlo;
    __nv_bfloat16 *qchi, *qclo, *kvhi, *kvlo, *ohi, *olo;
    float2* cstab;
    cudaGetSymbolAddress((void**)&xhi, g_xhi);
    cudaGetSymbolAddress((void**)&xlo, g_xlo);
    cudaGetSymbolAddress((void**)&qchi, g_qchi);
    cudaGetSymbolAddress((void**)&qclo, g_qclo);
    cudaGetSymbolAddress((void**)&kvhi, g_kvhi);
    cudaGetSymbolAddress((void**)&kvlo, g_kvlo);
    cudaGetSymbolAddress((void**)&ohi, g_ohi);
    cudaGetSymbolAddress((void**)&olo, g_olo);
    cudaGetSymbolAddress((void**)&wthi, g_wthi);
    cudaGetSymbolAddress((void**)&wtlo, g_wtlo);
    cudaGetSymbolAddress((void**)&cstab, g_cs);

    cudaFuncSetAttribute(gemm_hilo_kernel,
                         cudaFuncAttributeMaxDynamicSharedMemorySize, GK_SMEM_DYN);
    cudaFuncSetAttribute(flash_hmma_kernel,
                         cudaFuncAttributeMaxDynamicSharedMemorySize, FL_SMEM);

    dim3 tb(32, 8);
    const int nx = ROWS_TOT * D_DIM;
    const int ncs = S_LEN * (HD / 2);

    // Prep (bandwidth-bound)
    transpose_hilo_kernel<<<dim3(64, 64), tb>>>(Wq,  wthi + OFF_WQ,  wtlo + OFF_WQ,  2048, 2048);
    transpose_hilo_kernel<<<dim3(16, 64), tb>>>(Wdn, wthi + OFF_WDN, wtlo + OFF_WDN, 2048, 512);
    convert_hilo_kernel<<<nx / 256, 256>>>(x, xhi, xlo, nx);
    rope_table_kernel<<<(ncs + 255) / 256, 256>>>(freqs, cstab);
    transpose_hilo_kernel<<<dim3(64, 16), tb>>>(Wku, wthi + OFF_WKU, wtlo + OFF_WKU, 512, 2048);

    // Merged Q|c projection: x @ [Wq|Wdown], N=2560, RoPE on cols < 2048.
    gemm_hilo_kernel<<<GK_GRID, 256, GK_SMEM_DYN>>>(
        xhi, xlo, wthi + OFF_WQ, wtlo + OFF_WQ,
        nullptr, qchi, qclo, cstab, 2048,
        ROWS_TOT, QC_W, D_DIM, D_DIM, QC_W);

    transpose_hilo_kernel<<<dim3(64, 16), tb>>>(Wvu, wthi + OFF_WVU, wtlo + OFF_WVU, 512, 2048);
    transpose_hilo_kernel<<<dim3(64, 64), tb>>>(Wo,  wthi + OFF_WO,  wtlo + OFF_WO,  2048, 2048);

    // Merged K|V up-projection: c @ [Wkup|Wvup], N=4096, RoPE on cols < 2048.
    gemm_hilo_kernel<<<GK_GRID, 256, GK_SMEM_DYN>>>(
        qchi + 2048, qclo + 2048, wthi + OFF_WKU, wtlo + OFF_WKU,
        nullptr, kvhi, kvlo, cstab, 2048,
        ROWS_TOT, KV_W, LAT, QC_W, KV_W);

    // Flash attention (causal, HMMA hi/lo, staggered K/V, log2 softmax)
    flash_hmma_kernel<<<dim3(S_LEN / 64, BATCH * NH), 128, FL_SMEM>>>(
        qchi, qclo, kvhi, kvlo, ohi, olo);

    // Output projection (fp32 out)
    gemm_hilo_kernel<<<GK_GRID, 256, GK_SMEM_DYN>>>(
        ohi, olo, wthi + OFF_WO, wtlo + OFF_WO,
        out, nullptr, nullptr, nullptr, 0,
        ROWS_TOT, D_DIM, D_DIM, D_DIM, D_DIM);
}

// round 15
// speedup vs baseline: 1.0605x; 1.0156x over previous
#include <cuda_runtime.h>
#include <cuda_bf16.h>
#include <cstdint>
#include <math.h>

// Problem constants
#define BATCH   2
#define S_LEN   2048
#define D_DIM   2048
#define NH      16
#define HD      128
#define LAT     512
#define ROWS_TOT (BATCH * S_LEN)   // 4096
#define KV_W    4096               // merged K|V row width
#define QC_W    2560               // merged Q|c row width (2048 Q + 512 c)

// ---------------------------------------------------------------------------
// Scratch (__device__ globals; allocation-free rule)
// ---------------------------------------------------------------------------
__device__ __nv_bfloat16 g_xhi[ROWS_TOT * D_DIM];
__device__ __nv_bfloat16 g_xlo[ROWS_TOT * D_DIM];
__device__ __nv_bfloat16 g_qchi[ROWS_TOT * QC_W];   // [0,2048)=Q(roped), [2048,2560)=c
__device__ __nv_bfloat16 g_qclo[ROWS_TOT * QC_W];
__device__ __nv_bfloat16 g_kvhi[ROWS_TOT * KV_W];   // [0,2048)=K(roped), [2048,4096)=V
__device__ __nv_bfloat16 g_kvlo[ROWS_TOT * KV_W];
__device__ __nv_bfloat16 g_ohi[ROWS_TOT * D_DIM];
__device__ __nv_bfloat16 g_olo[ROWS_TOT * D_DIM];
__device__ float2 g_cs[S_LEN * (HD / 2)];           // RoPE cos/sin table

// Transposed-weight pool ([N,K] K-major bf16), hi and lo parts.
#define OFF_WQ  0
#define OFF_WDN 4194304
#define OFF_WKU 5242880
#define OFF_WVU 6291456
#define OFF_WO  7340032
#define WT_TOTAL 11534336
__device__ __nv_bfloat16 g_wthi[WT_TOTAL];
__device__ __nv_bfloat16 g_wtlo[WT_TOTAL];

// ---------------------------------------------------------------------------
// PTX helpers (sm_80+ features only — harness targets plain sm_103)
// ---------------------------------------------------------------------------
__device__ __forceinline__ uint32_t smem_u32(const void* p) {
    uint32_t a;
    asm("{ .reg .u64 t; cvta.to.shared.u64 t, %1; cvt.u32.u64 %0, t; }"
        : "=r"(a) : "l"(p));
    return a;
}
__device__ __forceinline__ void cp16(uint32_t dst, const void* src) {
    asm volatile("cp.async.cg.shared.global [%0], [%1], 16;" :: "r"(dst), "l"(src));
}
#define CP_COMMIT() asm volatile("cp.async.commit_group;" ::: "memory")

__device__ __forceinline__ void ldsm4(uint32_t& r0, uint32_t& r1,
                                      uint32_t& r2, uint32_t& r3, uint32_t a) {
    asm volatile("ldmatrix.sync.aligned.m8n8.x4.shared.b16 {%0,%1,%2,%3}, [%4];"
                 : "=r"(r0), "=r"(r1), "=r"(r2), "=r"(r3) : "r"(a));
}
__device__ __forceinline__ void ldsm4t(uint32_t& r0, uint32_t& r1,
                                       uint32_t& r2, uint32_t& r3, uint32_t a) {
    asm volatile("ldmatrix.sync.aligned.m8n8.x4.trans.shared.b16 {%0,%1,%2,%3}, [%4];"
                 : "=r"(r0), "=r"(r1), "=r"(r2), "=r"(r3) : "r"(a));
}
// Non-volatile: pure register op; lets ptxas interleave MMAs to break
// accumulator RAW chains.
__device__ __forceinline__ void mma16816(float* d, const uint32_t* a,
                                         uint32_t b0, uint32_t b1) {
    asm("mma.sync.aligned.m16n8k16.row.col.f32.bf16.bf16.f32 "
        "{%0,%1,%2,%3}, {%4,%5,%6,%7}, {%8,%9}, {%0,%1,%2,%3};"
        : "+f"(d[0]), "+f"(d[1]), "+f"(d[2]), "+f"(d[3])
        : "r"(a[0]), "r"(a[1]), "r"(a[2]), "r"(a[3]), "r"(b0), "r"(b1));
}
__device__ __forceinline__ uint32_t packbf2(__nv_bfloat16 x, __nv_bfloat16 y) {
    __nv_bfloat162 t(x, y);
    return *(uint32_t*)&t;
}
__device__ __forceinline__ float ex2(float x) {
    float r;
    asm("ex2.approx.f32 %0, %1;" : "=f"(r) : "f"(x));
    return r;
}

// XOR chunk swizzle for 64B-pitch rows (4 x 16B chunks per row).
__device__ __forceinline__ uint32_t swz64(int row, int chunk) {
    return (uint32_t)(row * 64 + ((chunk ^ ((row >> 1) & 3)) << 4));
}

// ---------------------------------------------------------------------------
// HMMA bf16 hi/lo GEMM (persistent). Round-14 (known-best): 3-stage ring,
// wait_group(1) slack, cross-tile stage rotation with next-tile prologue
// issued before the epilogue.
// ---------------------------------------------------------------------------
#define ST_AHI  0
#define ST_ALO  8192
#define ST_BHI  16384
#define ST_BLO  24576
#define STAGE_B 32768
#define GK_SMEM_DYN (3 * STAGE_B)   // 96 KB
#define GK_GRID 296                 // 2 CTAs x 148 SMs

__global__ __launch_bounds__(256, 2)
void gemm_hilo_kernel(const __nv_bfloat16* __restrict__ Ahi,
                      const __nv_bfloat16* __restrict__ Alo,
                      const __nv_bfloat16* __restrict__ Bhi,
                      const __nv_bfloat16* __restrict__ Blo,
                      float* __restrict__ Cout,
                      __nv_bfloat16* __restrict__ Chi,
                      __nv_bfloat16* __restrict__ Clo,
                      const float2* __restrict__ cstab,
                      int rope_cols,
                      int M, int N, int K, int lda, int ldc)
{
    extern __shared__ char dsm[];
    const uint32_t sbase = smem_u32(dsm);
    const int tid = threadIdx.x, lane = tid & 31, wid = tid >> 5;
    const int wm = wid & 3, wn = wid >> 2;           // 4 x 2 warp grid
    const int lrow = tid >> 1;
    const int lc0  = (tid & 1) * 2;
    const int lr = lane >> 2, lc = (lane & 3) * 2;
    const int nk = K >> 5;
    const int ntx = N >> 7;
    const int ntiles = (M >> 7) * ntx;

    auto load_stage = [&](int buf, int kc,
                          const __nv_bfloat16* Ah, const __nv_bfloat16* Al,
                          const __nv_bfloat16* Bh, const __nv_bfloat16* Bl) {
        const uint32_t st = sbase + buf * STAGE_B;
        const size_t koff = (size_t)kc * 32;
#pragma unroll
        for (int t = 0; t < 2; t++) {
            const int c = lc0 + t;
            const uint32_t doff = swz64(lrow, c);
            cp16(st + ST_AHI + doff, Ah + (size_t)lrow * lda + koff + c * 8);
            cp16(st + ST_ALO + doff, Al + (size_t)lrow * lda + koff + c * 8);
            cp16(st + ST_BHI + doff, Bh + (size_t)lrow * K + koff + c * 8);
            cp16(st + ST_BLO + doff, Bl + (size_t)lrow * K + koff + c * 8);
        }
        CP_COMMIT();
    };

    int tile = blockIdx.x;
    bool valid = tile < ntiles;
    int buf = 0;
    int m0 = 0, n0 = 0;
    const __nv_bfloat16 *cAh = Ahi, *cAl = Alo, *cBh = Bhi, *cBl = Blo;
    if (valid) {
        const int tyi = tile / ntx, txi = tile - tyi * ntx;
        m0 = tyi * 128; n0 = txi * 128;
        cAh = Ahi + (size_t)m0 * lda;
        cAl = Alo + (size_t)m0 * lda;
        cBh = Bhi + (size_t)n0 * K;
        cBl = Blo + (size_t)n0 * K;
        load_stage(0, 0, cAh, cAl, cBh, cBl);
        load_stage(1, 1, cAh, cAl, cBh, cBl);
    }

    while (valid) {
        float acc[2][8][4];
#pragma unroll
        for (int mt = 0; mt < 2; mt++)
#pragma unroll
            for (int nt = 0; nt < 8; nt++)
#pragma unroll
                for (int r = 0; r < 4; r++) acc[mt][nt][r] = 0.f;

        for (int k = 0; k < nk; k++) {
            if (k + 1 < nk)
                asm volatile("cp.async.wait_group 1;" ::: "memory");
            else
                asm volatile("cp.async.wait_group 0;" ::: "memory");
            __syncthreads();

            if (k + 2 < nk)
                load_stage((buf + k + 2) % 3, k + 2, cAh, cAl, cBh, cBl);

            const uint32_t st = sbase + ((buf + k) % 3) * STAGE_B;
#pragma unroll
            for (int ks = 0; ks < 2; ks++) {
                uint32_t ah[2][4], al[2][4];
#pragma unroll
                for (int mt = 0; mt < 2; mt++) {
                    const int row = wm * 32 + mt * 16 + (lane & 15);
                    const uint32_t off = swz64(row, ks * 2 + (lane >> 4));
                    ldsm4(ah[mt][0], ah[mt][1], ah[mt][2], ah[mt][3],
                          st + ST_AHI + off);
                    ldsm4(al[mt][0], al[mt][1], al[mt][2], al[mt][3],
                          st + ST_ALO + off);
                }
#pragma unroll
                for (int bp = 0; bp < 4; bp++) {
                    const int rn = wn * 64 + bp * 16 + ((lane >> 4) << 3) + (lane & 7);
                    const uint32_t off = swz64(rn, ks * 2 + ((lane >> 3) & 1));
                    uint32_t bh[4], bl[4];
                    ldsm4(bh[0], bh[1], bh[2], bh[3], st + ST_BHI + off);
                    ldsm4(bl[0], bl[1], bl[2], bl[3], st + ST_BLO + off);
#pragma unroll
                    for (int mt = 0; mt < 2; mt++)
#pragma unroll
                        for (int h = 0; h < 2; h++)
                            mma16816(acc[mt][2 * bp + h], ah[mt], bh[2 * h], bh[2 * h + 1]);
#pragma unroll
                    for (int mt = 0; mt < 2; mt++)
#pragma unroll
                        for (int h = 0; h < 2; h++)
                            mma16816(acc[mt][2 * bp + h], ah[mt], bl[2 * h], bl[2 * h + 1]);
#pragma unroll
                    for (int mt = 0; mt < 2; mt++)
#pragma unroll
                        for (int h = 0; h < 2; h++)
                            mma16816(acc[mt][2 * bp + h], al[mt], bh[2 * h], bh[2 * h + 1]);
                }
            }
        }

        buf = (buf + nk) % 3;
        const int ntile = tile + gridDim.x;
        const bool nvalid = ntile < ntiles;
        int nm0 = 0, nn0 = 0;
        const __nv_bfloat16 *nAh = cAh, *nAl = cAl, *nBh = cBh, *nBl = cBl;

        __syncthreads();   // all warps finished reading smem of this tile
        if (nvalid) {
            const int tyi = ntile / ntx, txi = ntile - tyi * ntx;
            nm0 = tyi * 128; nn0 = txi * 128;
            nAh = Ahi + (size_t)nm0 * lda;
            nAl = Alo + (size_t)nm0 * lda;
            nBh = Bhi + (size_t)nn0 * K;
            nBl = Blo + (size_t)nn0 * K;
            load_stage(buf, 0, nAh, nAl, nBh, nBl);
            load_stage((buf + 1) % 3, 1, nAh, nAl, nBh, nBl);
        }

        // ---- epilogue for current tile (hides next-tile load lead-in) ----
        const int rbase = m0 + wm * 32, cbase = n0 + wn * 64;
        if (Cout) {
#pragma unroll
            for (int mt = 0; mt < 2; mt++) {
#pragma unroll
                for (int nt = 0; nt < 8; nt++) {
                    float* d = acc[mt][nt];
                    const size_t r0 = (size_t)(rbase + mt * 16 + lr) * ldc
                                      + cbase + nt * 8 + lc;
                    *(float2*)(Cout + r0)           = make_float2(d[0], d[1]);
                    *(float2*)(Cout + r0 + 8 * ldc) = make_float2(d[2], d[3]);
                }
            }
        } else {
            const bool do_rope = (cstab != nullptr) && (cbase < rope_cols);
#pragma unroll
            for (int mt = 0; mt < 2; mt++) {
#pragma unroll
                for (int nt = 0; nt < 8; nt++) {
                    float* d = acc[mt][nt];
#pragma unroll
                    for (int half = 0; half < 2; half++) {
                        const int row = rbase + mt * 16 + lr + half * 8;
                        const int col = cbase + nt * 8 + lc;
                        float v0 = d[half * 2], v1 = d[half * 2 + 1];
                        if (do_rope) {
                            const int s = row & (S_LEN - 1);
                            const int p = (col & (HD - 1)) >> 1;
                            float2 cs = __ldg(cstab + s * (HD / 2) + p);
                            float r0 = v0 * cs.x - v1 * cs.y;
                            float r1 = v0 * cs.y + v1 * cs.x;
                            v0 = r0; v1 = r1;
                        }
                        __nv_bfloat16 h0 = __float2bfloat16(v0);
                        __nv_bfloat16 h1 = __float2bfloat16(v1);
                        const size_t o = (size_t)row * ldc + col;
                        *(uint32_t*)(Chi + o) = packbf2(h0, h1);
                        *(uint32_t*)(Clo + o) = packbf2(
                            __float2bfloat16(v0 - __bfloat162float(h0)),
                            __float2bfloat16(v1 - __bfloat162float(h1)));
                    }
                }
            }
        }

        tile = ntile;
        valid = nvalid;
        m0 = nm0; n0 = nn0;
        cAh = nAh; cAl = nAl; cBh = nBh; cBl = nBl;
    }
}

// ---------------------------------------------------------------------------
// Batched prep kernel: 5 weight transposes + x hi/lo convert + RoPE table
// in ONE launch. Block-range dispatcher; 256 threads per block.
//   [0, 4096)        Wq  transpose (2048x2048)
//   [4096, 5120)     Wdn transpose (2048x512)
//   [5120, 6144)     Wku transpose (512x2048)
//   [6144, 7168)     Wvu transpose (512x2048)
//   [7168, 11264)    Wo  transpose (2048x2048)
//   [11264, 19456)   x fp32 -> bf16 hi/lo (1024 elems/block, float4 loads)
//   [19456, 19968)   RoPE cos/sin table (256 entries/block)
// ---------------------------------------------------------------------------
#define PREP_GRID 19968

__global__ __launch_bounds__(256)
void prep_kernel(const float* __restrict__ x,
                 const float* __restrict__ freqs,
                 const float* __restrict__ Wq,
                 const float* __restrict__ Wdn,
                 const float* __restrict__ Wku,
                 const float* __restrict__ Wvu,
                 const float* __restrict__ Wo,
                 __nv_bfloat16* __restrict__ xhi,
                 __nv_bfloat16* __restrict__ xlo,
                 __nv_bfloat16* __restrict__ wthi,
                 __nv_bfloat16* __restrict__ wtlo,
                 float2* __restrict__ cstab)
{
    const int bid = blockIdx.x;
    const int tid = threadIdx.x;

    if (bid < 11264) {
        // ---- weight transpose: W[Kd,Nd] -> out[Nd,Kd] bf16 hi/lo ----
        const float* W; int ooff, Kd, Nd, base;
        if (bid < 4096)      { W = Wq;  ooff = OFF_WQ;  Kd = 2048; Nd = 2048; base = 0;    }
        else if (bid < 5120) { W = Wdn; ooff = OFF_WDN; Kd = 2048; Nd = 512;  base = 4096; }
        else if (bid < 6144) { W = Wku; ooff = OFF_WKU; Kd = 512;  Nd = 2048; base = 5120; }
        else if (bid < 7168) { W = Wvu; ooff = OFF_WVU; Kd = 512;  Nd = 2048; base = 6144; }
        else                 { W = Wo;  ooff = OFF_WO;  Kd = 2048; Nd = 2048; base = 7168; }
        __nv_bfloat16* hi = wthi + ooff;
        __nv_bfloat16* lo = wtlo + ooff;

        const int lidx = bid - base;
        const int gx = Nd >> 5;
        const int n0 = (lidx % gx) * 32;
        const int k0 = (lidx / gx) * 32;
        const int tx = tid & 31, ty = tid >> 5;   // 32 x 8

        __shared__ float t[32][33];
#pragma unroll
        for (int i = 0; i < 4; i++)
            t[ty + i * 8][tx] = W[(size_t)(k0 + ty + i * 8) * Nd + n0 + tx];
        __syncthreads();
#pragma unroll
        for (int i = 0; i < 4; i++) {
            float v = t[tx][ty + i * 8];
            __nv_bfloat16 h = __float2bfloat16(v);
            size_t o = (size_t)(n0 + ty + i * 8) * Kd + k0 + tx;
            hi[o] = h;
            lo[o] = __float2bfloat16(v - __bfloat162float(h));
        }
    } else if (bid < 19456) {
        // ---- x fp32 -> bf16 hi/lo, 1024 elems per block (float4 loads) ----
        const int i0 = (bid - 11264) * 1024 + tid * 4;
        float4 v4 = *(const float4*)(x + i0);
        float v[4] = {v4.x, v4.y, v4.z, v4.w};
        __nv_bfloat16 h[4], l[4];
#pragma unroll
        for (int j = 0; j < 4; j++) {
            h[j] = __float2bfloat16(v[j]);
            l[j] = __float2bfloat16(v[j] - __bfloat162float(h[j]));
        }
        *(uint32_t*)(xhi + i0)     = packbf2(h[0], h[1]);
        *(uint32_t*)(xhi + i0 + 2) = packbf2(h[2], h[3]);
        *(uint32_t*)(xlo + i0)     = packbf2(l[0], l[1]);
        *(uint32_t*)(xlo + i0 + 2) = packbf2(l[2], l[3]);
    } else {
        // ---- RoPE cos/sin table ----
        const int i = (bid - 19456) * 256 + tid;
        float f = freqs[i];
        float sn, cs;
        sincosf(f, &sn, &cs);
        cstab[i] = make_float2(cs, sn);
    }
}

// ---------------------------------------------------------------------------
// HMMA causal flash attention (round-14 design, known-best), bf16 hi/lo,
// log2-domain softmax, staggered K/V cp.async pipeline.
// BR=BC=64, 128 threads (4 warps x 16 q-rows).
// ---------------------------------------------------------------------------
#define FPB  272
#define SQHI 0
#define SQLO 17408
#define SKHI 34816
#define SKLO 52224
#define SVHI 69632
#define SVLO 87040
#define FL_SMEM 104448

__global__ __launch_bounds__(128)
void flash_hmma_kernel(const __nv_bfloat16* __restrict__ Qhi,
                       const __nv_bfloat16* __restrict__ Qlo,
                       const __nv_bfloat16* __restrict__ KVhi,
                       const __nv_bfloat16* __restrict__ KVlo,
                       __nv_bfloat16* __restrict__ Ohi,
                       __nv_bfloat16* __restrict__ Olo)
{
    extern __shared__ char dsm[];
    const uint32_t sb = smem_u32(dsm);

    const int tid = threadIdx.x, lane = tid & 31, wm = tid >> 5;
    const int lr = lane >> 2, lc2 = (lane & 3) * 2;

    const int bh_ = blockIdx.y;
    const int b = bh_ >> 4, head = bh_ & 15;
    const int qi = gridDim.x - 1 - blockIdx.x;       // heavy blocks first
    const int q0 = qi * 64;
    const size_t baseQ  = ((size_t)b * S_LEN) * QC_W + head * HD;
    const size_t baseKV = ((size_t)b * S_LEN) * KV_W + head * HD;
    const size_t baseO  = ((size_t)b * S_LEN) * D_DIM + head * HD;

    auto load_k = [&](int k0g) {
#pragma unroll
        for (int j = 0; j < 8; j++) {
            int lin = j * 128 + tid;
            int row = lin >> 4, c16 = lin & 15;
            const size_t so = baseKV + (size_t)(k0g + row) * KV_W + c16 * 8;
            const uint32_t doff = row * FPB + c16 * 16;
            cp16(sb + SKHI + doff, KVhi + so);
            cp16(sb + SKLO + doff, KVlo + so);
        }
        CP_COMMIT();
    };
    auto load_v = [&](int k0g) {
#pragma unroll
        for (int j = 0; j < 8; j++) {
            int lin = j * 128 + tid;
            int row = lin >> 4, c16 = lin & 15;
            const size_t so = baseKV + (size_t)(k0g + row) * KV_W + c16 * 8 + 2048;
            const uint32_t doff = row * FPB + c16 * 16;
            cp16(sb + SVHI + doff, KVhi + so);
            cp16(sb + SVLO + doff, KVlo + so);
        }
        CP_COMMIT();
    };

    // Prologue: Q, K0, V0 in flight (3 commit groups).
#pragma unroll
    for (int j = 0; j < 8; j++) {
        int lin = j * 128 + tid;
        int row = lin >> 4, c16 = lin & 15;
        const size_t so = baseQ + (size_t)(q0 + row) * QC_W + c16 * 8;
        const uint32_t doff = row * FPB + c16 * 16;
        cp16(sb + SQHI + doff, Qhi + so);
        cp16(sb + SQLO + doff, Qlo + so);
    }
    CP_COMMIT();
    load_k(0);
    load_v(0);

    float m[2] = {-1e30f, -1e30f}, l[2] = {0.f, 0.f};
    float accO[16][4];
#pragma unroll
    for (int nt = 0; nt < 16; nt++)
#pragma unroll
        for (int e = 0; e < 4; e++) accO[nt][e] = 0.f;

    // scale * log2(e): softmax carried in the log2 domain.
    const float scale2 = 0.08838834764831845f * 1.4426950408889634f;
    const int qrow_base = q0 + wm * 16;

    for (int kt = 0; kt <= qi; kt++) {
        const int k0g = kt * 64;
        const bool more = (kt < qi);

        // K_kt (and Q) complete; V_kt may still be in flight.
        asm volatile("cp.async.wait_group 1;" ::: "memory");
        __syncthreads();

        // ---- S = Q K^T ----
        float accS[8][4];
#pragma unroll
        for (int n = 0; n < 8; n++)
#pragma unroll
            for (int e = 0; e < 4; e++) accS[n][e] = 0.f;

#pragma unroll
        for (int ks = 0; ks < 8; ks++) {
            const int kk = ks * 16;
            uint32_t qh[4], ql[4];
            const uint32_t qoff = (wm * 16 + (lane & 15)) * FPB
                                  + (kk + ((lane >> 4) << 3)) * 2;
            ldsm4(qh[0], qh[1], qh[2], qh[3], sb + SQHI + qoff);
            ldsm4(ql[0], ql[1], ql[2], ql[3], sb + SQLO + qoff);
#pragma unroll
            for (int np = 0; np < 4; np++) {
                const uint32_t koff =
                    (np * 16 + (lane & 7) + ((lane >> 4) << 3)) * FPB
                    + (kk + (((lane >> 3) & 1) << 3)) * 2;
                uint32_t bh[4], bl[4];
                ldsm4(bh[0], bh[1], bh[2], bh[3], sb + SKHI + koff);
                ldsm4(bl[0], bl[1], bl[2], bl[3], sb + SKLO + koff);
#pragma unroll
                for (int t = 0; t < 2; t++)
                    mma16816(accS[np * 2 + t], qh, bh[2 * t], bh[2 * t + 1]);
#pragma unroll
                for (int t = 0; t < 2; t++)
                    mma16816(accS[np * 2 + t], qh, bl[2 * t], bl[2 * t + 1]);
#pragma unroll
                for (int t = 0; t < 2; t++)
                    mma16816(accS[np * 2 + t], ql, bh[2 * t], bh[2 * t + 1]);
            }
        }

        // All warps done reading the K tile; prefetch next K.
        __syncthreads();
        if (more) {
            load_k(k0g + 64);
            asm volatile("cp.async.wait_group 1;" ::: "memory");  // V_kt done
        } else {
            asm volatile("cp.async.wait_group 0;" ::: "memory");
        }
        __syncthreads();

        // ---- mask + log2-domain online softmax ----
        const bool diag = (kt == qi);
#pragma unroll
        for (int n = 0; n < 8; n++) {
#pragma unroll
            for (int e = 0; e < 4; e++) {
                float v = accS[n][e] * scale2;
                if (diag) {
                    int row = qrow_base + lr + 8 * (e >> 1);
                    int col = k0g + n * 8 + lc2 + (e & 1);
                    if (col > row) v = -1e30f;
                }
                accS[n][e] = v;
            }
        }

#pragma unroll
        for (int h = 0; h < 2; h++) {
            float mt = -1e30f;
#pragma unroll
            for (int n = 0; n < 8; n++)
                mt = fmaxf(mt, fmaxf(accS[n][2 * h], accS[n][2 * h + 1]));
            mt = fmaxf(mt, __shfl_xor_sync(0xffffffffu, mt, 1));
            mt = fmaxf(mt, __shfl_xor_sync(0xffffffffu, mt, 2));
            float mn = fmaxf(m[h], mt);
            float alpha = ex2(m[h] - mn);
            m[h] = mn;
            float lt = 0.f;
#pragma unroll
            for (int n = 0; n < 8; n++) {
                float p0 = ex2(accS[n][2 * h] - mn);
                float p1 = ex2(accS[n][2 * h + 1] - mn);
                accS[n][2 * h] = p0;
                accS[n][2 * h + 1] = p1;
                lt += p0 + p1;
            }
            lt += __shfl_xor_sync(0xffffffffu, lt, 1);
            lt += __shfl_xor_sync(0xffffffffu, lt, 2);
            l[h] = l[h] * alpha + lt;
#pragma unroll
            for (int nt = 0; nt < 16; nt++) {
                accO[nt][2 * h] *= alpha;
                accO[nt][2 * h + 1] *= alpha;
            }
        }

        // ---- O += P V ----
#pragma unroll
        for (int t = 0; t < 4; t++) {
            uint32_t phi[4], plo[4];
#pragma unroll
            for (int half = 0; half < 2; half++) {
                float* s = accS[2 * t + half];
#pragma unroll
                for (int rh = 0; rh < 2; rh++) {
                    float v0 = s[2 * rh], v1 = s[2 * rh + 1];
                    __nv_bfloat16 h0 = __float2bfloat16(v0);
                    __nv_bfloat16 h1 = __float2bfloat16(v1);
                    phi[half * 2 + rh] = packbf2(h0, h1);
                    plo[half * 2 + rh] = packbf2(
                        __float2bfloat16(v0 - __bfloat162float(h0)),
                        __float2bfloat16(v1 - __bfloat162float(h1)));
                }
            }
            const int kk = t * 16;
#pragma unroll
            for (int np = 0; np < 8; np++) {
                const uint32_t voff = (kk + (lane & 15)) * FPB
                                      + (np * 16 + ((lane >> 4) << 3)) * 2;
                uint32_t vh[4], vl[4];
                ldsm4t(vh[0], vh[1], vh[2], vh[3], sb + SVHI + voff);
                ldsm4t(vl[0], vl[1], vl[2], vl[3], sb + SVLO + voff);
#pragma unroll
                for (int u = 0; u < 2; u++)
                    mma16816(accO[np * 2 + u], phi, vh[2 * u], vh[2 * u + 1]);
#pragma unroll
                for (int u = 0; u < 2; u++)
                    mma16816(accO[np * 2 + u], phi, vl[2 * u], vl[2 * u + 1]);
#pragma unroll
                for (int u = 0; u < 2; u++)
                    mma16816(accO[np * 2 + u], plo, vh[2 * u], vh[2 * u + 1]);
            }
        }

        // All warps done reading the V tile; prefetch next V.
        if (more) {
            __syncthreads();
            load_v(k0g + 64);
        }
    }

    const float inv0 = 1.0f / l[0], inv1 = 1.0f / l[1];
#pragma unroll
    for (int nt = 0; nt < 16; nt++) {
#pragma unroll
        for (int h = 0; h < 2; h++) {
            float inv = h ? inv1 : inv0;
            float v0 = accO[nt][2 * h] * inv;
            float v1 = accO[nt][2 * h + 1] * inv;
            __nv_bfloat16 h0 = __float2bfloat16(v0);
            __nv_bfloat16 h1 = __float2bfloat16(v1);
            const size_t o = baseO
                + (size_t)(qrow_base + lr + 8 * h) * D_DIM + nt * 8 + lc2;
            *(uint32_t*)(Ohi + o) = packbf2(h0, h1);
            *(uint32_t*)(Olo + o) = packbf2(
                __float2bfloat16(v0 - __bfloat162float(h0)),
                __float2bfloat16(v1 - __bfloat162float(h1)));
        }
    }
}

// ---------------------------------------------------------------------------
// Launch
// Inputs: x, freqs, mask(unused: exactly causal), Wq, Wdown, Wkup, Wvup, Wo
// ---------------------------------------------------------------------------
extern "C" void kernel_launch(void* const* d_in, const int* in_sizes, int n_in,
                              void* d_out, int out_size)
{
    const float* x     = (const float*)d_in[0];
    const float* freqs = (const float*)d_in[1];
    const float* Wq    = (const float*)d_in[3];
    const float* Wdn   = (const float*)d_in[4];
    const float* Wku   = (const float*)d_in[5];
    const float* Wvu   = (const float*)d_in[6];
    const float* Wo    = (const float*)d_in[7];
    float* out = (float*)d_out;

    __nv_bfloat16 *xhi, *xlo, *wthi, *wtlo;
    __nv_bfloat16 *qchi, *qclo, *kvhi, *kvlo, *ohi, *olo;
    float2* cstab;
    cudaGetSymbolAddress((void**)&xhi, g_xhi);
    cudaGetSymbolAddress((void**)&xlo, g_xlo);
    cudaGetSymbolAddress((void**)&qchi, g_qchi);
    cudaGetSymbolAddress((void**)&qclo, g_qclo);
    cudaGetSymbolAddress((void**)&kvhi, g_kvhi);
    cudaGetSymbolAddress((void**)&kvlo, g_kvlo);
    cudaGetSymbolAddress((void**)&ohi, g_ohi);
    cudaGetSymbolAddress((void**)&olo, g_olo);
    cudaGetSymbolAddress((void**)&wthi, g_wthi);
    cudaGetSymbolAddress((void**)&wtlo, g_wtlo);
    cudaGetSymbolAddress((void**)&cstab, g_cs);

    cudaFuncSetAttribute(gemm_hilo_kernel,
                         cudaFuncAttributeMaxDynamicSharedMemorySize, GK_SMEM_DYN);
    cudaFuncSetAttribute(flash_hmma_kernel,
                         cudaFuncAttributeMaxDynamicSharedMemorySize, FL_SMEM);

    // Single batched prep launch: all transposes + x convert + RoPE table.
    prep_kernel<<<PREP_GRID, 256>>>(x, freqs, Wq, Wdn, Wku, Wvu, Wo,
                                    xhi, xlo, wthi, wtlo, cstab);

    // Merged Q|c projection: x @ [Wq|Wdown], N=2560, RoPE on cols < 2048.
    gemm_hilo_kernel<<<GK_GRID, 256, GK_SMEM_DYN>>>(
        xhi, xlo, wthi + OFF_WQ, wtlo + OFF_WQ,
        nullptr, qchi, qclo, cstab, 2048,
        ROWS_TOT, QC_W, D_DIM, D_DIM, QC_W);

    // Merged K|V up-projection: c @ [Wkup|Wvup], N=4096, RoPE on cols < 2048.
    gemm_hilo_kernel<<<GK_GRID, 256, GK_SMEM_DYN>>>(
        qchi + 2048, qclo + 2048, wthi + OFF_WKU, wtlo + OFF_WKU,
        nullptr, kvhi, kvlo, cstab, 2048,
        ROWS_TOT, KV_W, LAT, QC_W, KV_W);

    // Flash attention (causal, HMMA hi/lo, staggered K/V, log2 softmax)
    flash_hmma_kernel<<<dim3(S_LEN / 64, BATCH * NH), 128, FL_SMEM>>>(
        qchi, qclo, kvhi, kvlo, ohi, olo);

    // Output projection (fp32 out)
    gemm_hilo_kernel<<<GK_GRID, 256, GK_SMEM_DYN>>>(
        ohi, olo, wthi + OFF_WO, wtlo + OFF_WO,
        out, nullptr, nullptr, nullptr, 0,
        ROWS_TOT, D_DIM, D_DIM, D_DIM, D_DIM);
}

// round 16
// speedup vs baseline: 1.0655x; 1.0047x over previous
#include <cuda_runtime.h>
#include <cuda_bf16.h>
#include <cstdint>
#include <math.h>

// Problem constants
#define BATCH   2
#define S_LEN   2048
#define D_DIM   2048
#define NH      16
#define HD      128
#define LAT     512
#define ROWS_TOT (BATCH * S_LEN)   // 4096
#define KV_W    4096               // merged K|V row width
#define QC_W    2560               // merged Q|c row width (2048 Q + 512 c)

// ---------------------------------------------------------------------------
// Scratch (__device__ globals; allocation-free rule)
// ---------------------------------------------------------------------------
__device__ __nv_bfloat16 g_xhi[ROWS_TOT * D_DIM];
__device__ __nv_bfloat16 g_xlo[ROWS_TOT * D_DIM];
__device__ __nv_bfloat16 g_qchi[ROWS_TOT * QC_W];   // [0,2048)=Q(roped), [2048,2560)=c
__device__ __nv_bfloat16 g_qclo[ROWS_TOT * QC_W];
__device__ __nv_bfloat16 g_kvhi[ROWS_TOT * KV_W];   // [0,2048)=K(roped), [2048,4096)=V
__device__ __nv_bfloat16 g_kvlo[ROWS_TOT * KV_W];
__device__ __nv_bfloat16 g_ohi[ROWS_TOT * D_DIM];
__device__ __nv_bfloat16 g_olo[ROWS_TOT * D_DIM];
__device__ float2 g_cs[S_LEN * (HD / 2)];           // RoPE cos/sin table

// Transposed-weight pool ([N,K] K-major bf16), hi and lo parts.
#define OFF_WQ  0
#define OFF_WDN 4194304
#define OFF_WKU 5242880
#define OFF_WVU 6291456
#define OFF_WO  7340032
#define WT_TOTAL 11534336
__device__ __nv_bfloat16 g_wthi[WT_TOTAL];
__device__ __nv_bfloat16 g_wtlo[WT_TOTAL];

// ---------------------------------------------------------------------------
// PTX helpers (sm_80+ features only — harness targets plain sm_103)
// ---------------------------------------------------------------------------
__device__ __forceinline__ uint32_t smem_u32(const void* p) {
    uint32_t a;
    asm("{ .reg .u64 t; cvta.to.shared.u64 t, %1; cvt.u32.u64 %0, t; }"
        : "=r"(a) : "l"(p));
    return a;
}
__device__ __forceinline__ void cp16(uint32_t dst, const void* src) {
    asm volatile("cp.async.cg.shared.global [%0], [%1], 16;" :: "r"(dst), "l"(src));
}
#define CP_COMMIT() asm volatile("cp.async.commit_group;" ::: "memory")

__device__ __forceinline__ void ldsm4(uint32_t& r0, uint32_t& r1,
                                      uint32_t& r2, uint32_t& r3, uint32_t a) {
    asm volatile("ldmatrix.sync.aligned.m8n8.x4.shared.b16 {%0,%1,%2,%3}, [%4];"
                 : "=r"(r0), "=r"(r1), "=r"(r2), "=r"(r3) : "r"(a));
}
__device__ __forceinline__ void ldsm4t(uint32_t& r0, uint32_t& r1,
                                       uint32_t& r2, uint32_t& r3, uint32_t a) {
    asm volatile("ldmatrix.sync.aligned.m8n8.x4.trans.shared.b16 {%0,%1,%2,%3}, [%4];"
                 : "=r"(r0), "=r"(r1), "=r"(r2), "=r"(r3) : "r"(a));
}
// Non-volatile: pure register op; lets ptxas interleave MMAs to break
// accumulator RAW chains.
__device__ __forceinline__ void mma16816(float* d, const uint32_t* a,
                                         uint32_t b0, uint32_t b1) {
    asm("mma.sync.aligned.m16n8k16.row.col.f32.bf16.bf16.f32 "
        "{%0,%1,%2,%3}, {%4,%5,%6,%7}, {%8,%9}, {%0,%1,%2,%3};"
        : "+f"(d[0]), "+f"(d[1]), "+f"(d[2]), "+f"(d[3])
        : "r"(a[0]), "r"(a[1]), "r"(a[2]), "r"(a[3]), "r"(b0), "r"(b1));
}
__device__ __forceinline__ uint32_t packbf2(__nv_bfloat16 x, __nv_bfloat16 y) {
    __nv_bfloat162 t(x, y);
    return *(uint32_t*)&t;
}
__device__ __forceinline__ float ex2(float x) {
    float r;
    asm("ex2.approx.f32 %0, %1;" : "=f"(r) : "f"(x));
    return r;
}

// XOR chunk swizzle for 64B-pitch rows (4 x 16B chunks per row).
__device__ __forceinline__ uint32_t swz64(int row, int chunk) {
    return (uint32_t)(row * 64 + ((chunk ^ ((row >> 1) & 3)) << 4));
}

// ---------------------------------------------------------------------------
// HMMA bf16 hi/lo GEMM (persistent). Round-14/15 (known-best).
// ---------------------------------------------------------------------------
#define ST_AHI  0
#define ST_ALO  8192
#define ST_BHI  16384
#define ST_BLO  24576
#define STAGE_B 32768
#define GK_SMEM_DYN (3 * STAGE_B)   // 96 KB
#define GK_GRID 296                 // 2 CTAs x 148 SMs

__global__ __launch_bounds__(256, 2)
void gemm_hilo_kernel(const __nv_bfloat16* __restrict__ Ahi,
                      const __nv_bfloat16* __restrict__ Alo,
                      const __nv_bfloat16* __restrict__ Bhi,
                      const __nv_bfloat16* __restrict__ Blo,
                      float* __restrict__ Cout,
                      __nv_bfloat16* __restrict__ Chi,
                      __nv_bfloat16* __restrict__ Clo,
                      const float2* __restrict__ cstab,
                      int rope_cols,
                      int M, int N, int K, int lda, int ldc)
{
    extern __shared__ char dsm[];
    const uint32_t sbase = smem_u32(dsm);
    const int tid = threadIdx.x, lane = tid & 31, wid = tid >> 5;
    const int wm = wid & 3, wn = wid >> 2;           // 4 x 2 warp grid
    const int lrow = tid >> 1;
    const int lc0  = (tid & 1) * 2;
    const int lr = lane >> 2, lc = (lane & 3) * 2;
    const int nk = K >> 5;
    const int ntx = N >> 7;
    const int ntiles = (M >> 7) * ntx;

    auto load_stage = [&](int buf, int kc,
                          const __nv_bfloat16* Ah, const __nv_bfloat16* Al,
                          const __nv_bfloat16* Bh, const __nv_bfloat16* Bl) {
        const uint32_t st = sbase + buf * STAGE_B;
        const size_t koff = (size_t)kc * 32;
#pragma unroll
        for (int t = 0; t < 2; t++) {
            const int c = lc0 + t;
            const uint32_t doff = swz64(lrow, c);
            cp16(st + ST_AHI + doff, Ah + (size_t)lrow * lda + koff + c * 8);
            cp16(st + ST_ALO + doff, Al + (size_t)lrow * lda + koff + c * 8);
            cp16(st + ST_BHI + doff, Bh + (size_t)lrow * K + koff + c * 8);
            cp16(st + ST_BLO + doff, Bl + (size_t)lrow * K + koff + c * 8);
        }
        CP_COMMIT();
    };

    int tile = blockIdx.x;
    bool valid = tile < ntiles;
    int buf = 0;
    int m0 = 0, n0 = 0;
    const __nv_bfloat16 *cAh = Ahi, *cAl = Alo, *cBh = Bhi, *cBl = Blo;
    if (valid) {
        const int tyi = tile / ntx, txi = tile - tyi * ntx;
        m0 = tyi * 128; n0 = txi * 128;
        cAh = Ahi + (size_t)m0 * lda;
        cAl = Alo + (size_t)m0 * lda;
        cBh = Bhi + (size_t)n0 * K;
        cBl = Blo + (size_t)n0 * K;
        load_stage(0, 0, cAh, cAl, cBh, cBl);
        load_stage(1, 1, cAh, cAl, cBh, cBl);
    }

    while (valid) {
        float acc[2][8][4];
#pragma unroll
        for (int mt = 0; mt < 2; mt++)
#pragma unroll
            for (int nt = 0; nt < 8; nt++)
#pragma unroll
                for (int r = 0; r < 4; r++) acc[mt][nt][r] = 0.f;

        for (int k = 0; k < nk; k++) {
            if (k + 1 < nk)
                asm volatile("cp.async.wait_group 1;" ::: "memory");
            else
                asm volatile("cp.async.wait_group 0;" ::: "memory");
            __syncthreads();

            if (k + 2 < nk)
                load_stage((buf + k + 2) % 3, k + 2, cAh, cAl, cBh, cBl);

            const uint32_t st = sbase + ((buf + k) % 3) * STAGE_B;
#pragma unroll
            for (int ks = 0; ks < 2; ks++) {
                uint32_t ah[2][4], al[2][4];
#pragma unroll
                for (int mt = 0; mt < 2; mt++) {
                    const int row = wm * 32 + mt * 16 + (lane & 15);
                    const uint32_t off = swz64(row, ks * 2 + (lane >> 4));
                    ldsm4(ah[mt][0], ah[mt][1], ah[mt][2], ah[mt][3],
                          st + ST_AHI + off);
                    ldsm4(al[mt][0], al[mt][1], al[mt][2], al[mt][3],
                          st + ST_ALO + off);
                }
#pragma unroll
                for (int bp = 0; bp < 4; bp++) {
                    const int rn = wn * 64 + bp * 16 + ((lane >> 4) << 3) + (lane & 7);
                    const uint32_t off = swz64(rn, ks * 2 + ((lane >> 3) & 1));
                    uint32_t bh[4], bl[4];
                    ldsm4(bh[0], bh[1], bh[2], bh[3], st + ST_BHI + off);
                    ldsm4(bl[0], bl[1], bl[2], bl[3], st + ST_BLO + off);
#pragma unroll
                    for (int mt = 0; mt < 2; mt++)
#pragma unroll
                        for (int h = 0; h < 2; h++)
                            mma16816(acc[mt][2 * bp + h], ah[mt], bh[2 * h], bh[2 * h + 1]);
#pragma unroll
                    for (int mt = 0; mt < 2; mt++)
#pragma unroll
                        for (int h = 0; h < 2; h++)
                            mma16816(acc[mt][2 * bp + h], ah[mt], bl[2 * h], bl[2 * h + 1]);
#pragma unroll
                    for (int mt = 0; mt < 2; mt++)
#pragma unroll
                        for (int h = 0; h < 2; h++)
                            mma16816(acc[mt][2 * bp + h], al[mt], bh[2 * h], bh[2 * h + 1]);
                }
            }
        }

        buf = (buf + nk) % 3;
        const int ntile = tile + gridDim.x;
        const bool nvalid = ntile < ntiles;
        int nm0 = 0, nn0 = 0;
        const __nv_bfloat16 *nAh = cAh, *nAl = cAl, *nBh = cBh, *nBl = cBl;

        __syncthreads();   // all warps finished reading smem of this tile
        if (nvalid) {
            const int tyi = ntile / ntx, txi = ntile - tyi * ntx;
            nm0 = tyi * 128; nn0 = txi * 128;
            nAh = Ahi + (size_t)nm0 * lda;
            nAl = Alo + (size_t)nm0 * lda;
            nBh = Bhi + (size_t)nn0 * K;
            nBl = Blo + (size_t)nn0 * K;
            load_stage(buf, 0, nAh, nAl, nBh, nBl);
            load_stage((buf + 1) % 3, 1, nAh, nAl, nBh, nBl);
        }

        // ---- epilogue for current tile (hides next-tile load lead-in) ----
        const int rbase = m0 + wm * 32, cbase = n0 + wn * 64;
        if (Cout) {
#pragma unroll
            for (int mt = 0; mt < 2; mt++) {
#pragma unroll
                for (int nt = 0; nt < 8; nt++) {
                    float* d = acc[mt][nt];
                    const size_t r0 = (size_t)(rbase + mt * 16 + lr) * ldc
                                      + cbase + nt * 8 + lc;
                    *(float2*)(Cout + r0)           = make_float2(d[0], d[1]);
                    *(float2*)(Cout + r0 + 8 * ldc) = make_float2(d[2], d[3]);
                }
            }
        } else {
            const bool do_rope = (cstab != nullptr) && (cbase < rope_cols);
#pragma unroll
            for (int mt = 0; mt < 2; mt++) {
#pragma unroll
                for (int nt = 0; nt < 8; nt++) {
                    float* d = acc[mt][nt];
#pragma unroll
                    for (int half = 0; half < 2; half++) {
                        const int row = rbase + mt * 16 + lr + half * 8;
                        const int col = cbase + nt * 8 + lc;
                        float v0 = d[half * 2], v1 = d[half * 2 + 1];
                        if (do_rope) {
                            const int s = row & (S_LEN - 1);
                            const int p = (col & (HD - 1)) >> 1;
                            float2 cs = __ldg(cstab + s * (HD / 2) + p);
                            float r0 = v0 * cs.x - v1 * cs.y;
                            float r1 = v0 * cs.y + v1 * cs.x;
                            v0 = r0; v1 = r1;
                        }
                        __nv_bfloat16 h0 = __float2bfloat16(v0);
                        __nv_bfloat16 h1 = __float2bfloat16(v1);
                        const size_t o = (size_t)row * ldc + col;
                        *(uint32_t*)(Chi + o) = packbf2(h0, h1);
                        *(uint32_t*)(Clo + o) = packbf2(
                            __float2bfloat16(v0 - __bfloat162float(h0)),
                            __float2bfloat16(v1 - __bfloat162float(h1)));
                    }
                }
            }
        }

        tile = ntile;
        valid = nvalid;
        m0 = nm0; n0 = nn0;
        cAh = nAh; cAl = nAl; cBh = nBh; cBl = nBl;
    }
}

// ---------------------------------------------------------------------------
// Batched prep kernel (round-15, known-good).
// ---------------------------------------------------------------------------
#define PREP_GRID 19968

__global__ __launch_bounds__(256)
void prep_kernel(const float* __restrict__ x,
                 const float* __restrict__ freqs,
                 const float* __restrict__ Wq,
                 const float* __restrict__ Wdn,
                 const float* __restrict__ Wku,
                 const float* __restrict__ Wvu,
                 const float* __restrict__ Wo,
                 __nv_bfloat16* __restrict__ xhi,
                 __nv_bfloat16* __restrict__ xlo,
                 __nv_bfloat16* __restrict__ wthi,
                 __nv_bfloat16* __restrict__ wtlo,
                 float2* __restrict__ cstab)
{
    const int bid = blockIdx.x;
    const int tid = threadIdx.x;

    if (bid < 11264) {
        const float* W; int ooff, Kd, Nd, base;
        if (bid < 4096)      { W = Wq;  ooff = OFF_WQ;  Kd = 2048; Nd = 2048; base = 0;    }
        else if (bid < 5120) { W = Wdn; ooff = OFF_WDN; Kd = 2048; Nd = 512;  base = 4096; }
        else if (bid < 6144) { W = Wku; ooff = OFF_WKU; Kd = 512;  Nd = 2048; base = 5120; }
        else if (bid < 7168) { W = Wvu; ooff = OFF_WVU; Kd = 512;  Nd = 2048; base = 6144; }
        else                 { W = Wo;  ooff = OFF_WO;  Kd = 2048; Nd = 2048; base = 7168; }
        __nv_bfloat16* hi = wthi + ooff;
        __nv_bfloat16* lo = wtlo + ooff;

        const int lidx = bid - base;
        const int gx = Nd >> 5;
        const int n0 = (lidx % gx) * 32;
        const int k0 = (lidx / gx) * 32;
        const int tx = tid & 31, ty = tid >> 5;

        __shared__ float t[32][33];
#pragma unroll
        for (int i = 0; i < 4; i++)
            t[ty + i * 8][tx] = W[(size_t)(k0 + ty + i * 8) * Nd + n0 + tx];
        __syncthreads();
#pragma unroll
        for (int i = 0; i < 4; i++) {
            float v = t[tx][ty + i * 8];
            __nv_bfloat16 h = __float2bfloat16(v);
            size_t o = (size_t)(n0 + ty + i * 8) * Kd + k0 + tx;
            hi[o] = h;
            lo[o] = __float2bfloat16(v - __bfloat162float(h));
        }
    } else if (bid < 19456) {
        const int i0 = (bid - 11264) * 1024 + tid * 4;
        float4 v4 = *(const float4*)(x + i0);
        float v[4] = {v4.x, v4.y, v4.z, v4.w};
        __nv_bfloat16 h[4], l[4];
#pragma unroll
        for (int j = 0; j < 4; j++) {
            h[j] = __float2bfloat16(v[j]);
            l[j] = __float2bfloat16(v[j] - __bfloat162float(h[j]));
        }
        *(uint32_t*)(xhi + i0)     = packbf2(h[0], h[1]);
        *(uint32_t*)(xhi + i0 + 2) = packbf2(h[2], h[3]);
        *(uint32_t*)(xlo + i0)     = packbf2(l[0], l[1]);
        *(uint32_t*)(xlo + i0 + 2) = packbf2(l[2], l[3]);
    } else {
        const int i = (bid - 19456) * 256 + tid;
        float f = freqs[i];
        float sn, cs;
        sincosf(f, &sn, &cs);
        cstab[i] = make_float2(cs, sn);
    }
}

// ---------------------------------------------------------------------------
// HMMA causal flash attention v3: BR=64, BC=32, 128 threads (4 warps x 16
// q-rows, warp-private softmax), log2-domain softmax, staggered K/V pipeline.
// smem 68KB => 3 CTAs/SM = 12 warps/SM (was 8) to feed the tensor pipe.
// ---------------------------------------------------------------------------
#define FPB  272
#define SQHI 0
#define SQLO 17408
#define SKHI 34816
#define SKLO 43520
#define SVHI 52224
#define SVLO 60928
#define FL_SMEM 69632

__global__ __launch_bounds__(128, 3)
void flash_hmma_kernel(const __nv_bfloat16* __restrict__ Qhi,
                       const __nv_bfloat16* __restrict__ Qlo,
                       const __nv_bfloat16* __restrict__ KVhi,
                       const __nv_bfloat16* __restrict__ KVlo,
                       __nv_bfloat16* __restrict__ Ohi,
                       __nv_bfloat16* __restrict__ Olo)
{
    extern __shared__ char dsm[];
    const uint32_t sb = smem_u32(dsm);

    const int tid = threadIdx.x, lane = tid & 31, wm = tid >> 5;
    const int lr = lane >> 2, lc2 = (lane & 3) * 2;

    const int bh_ = blockIdx.y;
    const int b = bh_ >> 4, head = bh_ & 15;
    const int qi = gridDim.x - 1 - blockIdx.x;       // heavy blocks first
    const int q0 = qi * 64;
    const size_t baseQ  = ((size_t)b * S_LEN) * QC_W + head * HD;
    const size_t baseKV = ((size_t)b * S_LEN) * KV_W + head * HD;
    const size_t baseO  = ((size_t)b * S_LEN) * D_DIM + head * HD;

    auto load_k = [&](int k0g) {
#pragma unroll
        for (int j = 0; j < 4; j++) {
            int lin = j * 128 + tid;
            int row = lin >> 4, c16 = lin & 15;   // 32 rows x 16 chunks
            const size_t so = baseKV + (size_t)(k0g + row) * KV_W + c16 * 8;
            const uint32_t doff = row * FPB + c16 * 16;
            cp16(sb + SKHI + doff, KVhi + so);
            cp16(sb + SKLO + doff, KVlo + so);
        }
        CP_COMMIT();
    };
    auto load_v = [&](int k0g) {
#pragma unroll
        for (int j = 0; j < 4; j++) {
            int lin = j * 128 + tid;
            int row = lin >> 4, c16 = lin & 15;
            const size_t so = baseKV + (size_t)(k0g + row) * KV_W + c16 * 8 + 2048;
            const uint32_t doff = row * FPB + c16 * 16;
            cp16(sb + SVHI + doff, KVhi + so);
            cp16(sb + SVLO + doff, KVlo + so);
        }
        CP_COMMIT();
    };

    // Prologue: Q (64 rows), K0, V0 in flight (3 commit groups).
#pragma unroll
    for (int j = 0; j < 8; j++) {
        int lin = j * 128 + tid;
        int row = lin >> 4, c16 = lin & 15;
        const size_t so = baseQ + (size_t)(q0 + row) * QC_W + c16 * 8;
        const uint32_t doff = row * FPB + c16 * 16;
        cp16(sb + SQHI + doff, Qhi + so);
        cp16(sb + SQLO + doff, Qlo + so);
    }
    CP_COMMIT();
    load_k(0);
    load_v(0);

    float m[2] = {-1e30f, -1e30f}, l[2] = {0.f, 0.f};
    float accO[16][4];
#pragma unroll
    for (int nt = 0; nt < 16; nt++)
#pragma unroll
        for (int e = 0; e < 4; e++) accO[nt][e] = 0.f;

    const float scale2 = 0.08838834764831845f * 1.4426950408889634f;
    const int qrow_base = q0 + wm * 16;
    const int nkt = 2 * (qi + 1);                    // 32-wide K blocks

    for (int kt = 0; kt < nkt; kt++) {
        const int k0g = kt * 32;
        const bool more = (kt + 1 < nkt);

        // K_kt (and Q) complete; V_kt may still be in flight.
        asm volatile("cp.async.wait_group 1;" ::: "memory");
        __syncthreads();

        // ---- S = Q K^T (64 rows x 32 cols; warp owns 16 rows) ----
        float accS[4][4];
#pragma unroll
        for (int n = 0; n < 4; n++)
#pragma unroll
            for (int e = 0; e < 4; e++) accS[n][e] = 0.f;

#pragma unroll
        for (int ks = 0; ks < 8; ks++) {
            const int kk = ks * 16;
            uint32_t qh[4], ql[4];
            const uint32_t qoff = (wm * 16 + (lane & 15)) * FPB
                                  + (kk + ((lane >> 4) << 3)) * 2;
            ldsm4(qh[0], qh[1], qh[2], qh[3], sb + SQHI + qoff);
            ldsm4(ql[0], ql[1], ql[2], ql[3], sb + SQLO + qoff);
#pragma unroll
            for (int np = 0; np < 2; np++) {
                const uint32_t koff =
                    (np * 16 + (lane & 7) + ((lane >> 4) << 3)) * FPB
                    + (kk + (((lane >> 3) & 1) << 3)) * 2;
                uint32_t bh[4], bl[4];
                ldsm4(bh[0], bh[1], bh[2], bh[3], sb + SKHI + koff);
                ldsm4(bl[0], bl[1], bl[2], bl[3], sb + SKLO + koff);
#pragma unroll
                for (int t = 0; t < 2; t++)
                    mma16816(accS[np * 2 + t], qh, bh[2 * t], bh[2 * t + 1]);
#pragma unroll
                for (int t = 0; t < 2; t++)
                    mma16816(accS[np * 2 + t], qh, bl[2 * t], bl[2 * t + 1]);
#pragma unroll
                for (int t = 0; t < 2; t++)
                    mma16816(accS[np * 2 + t], ql, bh[2 * t], bh[2 * t + 1]);
            }
        }

        // All warps done reading the K tile; prefetch next K.
        __syncthreads();
        if (more) {
            load_k(k0g + 32);
            asm volatile("cp.async.wait_group 1;" ::: "memory");  // V_kt done
        } else {
            asm volatile("cp.async.wait_group 0;" ::: "memory");
        }
        __syncthreads();

        // ---- mask + log2-domain online softmax (warp-private) ----
        const bool diag = (k0g + 32 > qrow_base);
#pragma unroll
        for (int n = 0; n < 4; n++) {
#pragma unroll
            for (int e = 0; e < 4; e++) {
                float v = accS[n][e] * scale2;
                if (diag) {
                    int row = qrow_base + lr + 8 * (e >> 1);
                    int col = k0g + n * 8 + lc2 + (e & 1);
                    if (col > row) v = -1e30f;
                }
                accS[n][e] = v;
            }
        }

#pragma unroll
        for (int h = 0; h < 2; h++) {
            float mt = -1e30f;
#pragma unroll
            for (int n = 0; n < 4; n++)
                mt = fmaxf(mt, fmaxf(accS[n][2 * h], accS[n][2 * h + 1]));
            mt = fmaxf(mt, __shfl_xor_sync(0xffffffffu, mt, 1));
            mt = fmaxf(mt, __shfl_xor_sync(0xffffffffu, mt, 2));
            float mn = fmaxf(m[h], mt);
            float alpha = ex2(m[h] - mn);
            m[h] = mn;
            float lt = 0.f;
#pragma unroll
            for (int n = 0; n < 4; n++) {
                float p0 = ex2(accS[n][2 * h] - mn);
                float p1 = ex2(accS[n][2 * h + 1] - mn);
                accS[n][2 * h] = p0;
                accS[n][2 * h + 1] = p1;
                lt += p0 + p1;
            }
            lt += __shfl_xor_sync(0xffffffffu, lt, 1);
            lt += __shfl_xor_sync(0xffffffffu, lt, 2);
            l[h] = l[h] * alpha + lt;
#pragma unroll
            for (int nt = 0; nt < 16; nt++) {
                accO[nt][2 * h] *= alpha;
                accO[nt][2 * h + 1] *= alpha;
            }
        }

        // ---- O += P V (k-dim 32: 2 k-steps) ----
#pragma unroll
        for (int t = 0; t < 2; t++) {
            uint32_t phi[4], plo[4];
#pragma unroll
            for (int half = 0; half < 2; half++) {
                float* s = accS[2 * t + half];
#pragma unroll
                for (int rh = 0; rh < 2; rh++) {
                    float v0 = s[2 * rh], v1 = s[2 * rh + 1];
                    __nv_bfloat16 h0 = __float2bfloat16(v0);
                    __nv_bfloat16 h1 = __float2bfloat16(v1);
                    phi[half * 2 + rh] = packbf2(h0, h1);
                    plo[half * 2 + rh] = packbf2(
                        __float2bfloat16(v0 - __bfloat162float(h0)),
                        __float2bfloat16(v1 - __bfloat162float(h1)));
                }
            }
            const int kk = t * 16;
#pragma unroll
            for (int np = 0; np < 8; np++) {
                const uint32_t voff = (kk + (lane & 15)) * FPB
                                      + (np * 16 + ((lane >> 4) << 3)) * 2;
                uint32_t vh[4], vl[4];
                ldsm4t(vh[0], vh[1], vh[2], vh[3], sb + SVHI + voff);
                ldsm4t(vl[0], vl[1], vl[2], vl[3], sb + SVLO + voff);
#pragma unroll
                for (int u = 0; u < 2; u++)
                    mma16816(accO[np * 2 + u], phi, vh[2 * u], vh[2 * u + 1]);
#pragma unroll
                for (int u = 0; u < 2; u++)
                    mma16816(accO[np * 2 + u], phi, vl[2 * u], vl[2 * u + 1]);
#pragma unroll
                for (int u = 0; u < 2; u++)
                    mma16816(accO[np * 2 + u], plo, vh[2 * u], vh[2 * u + 1]);
            }
        }

        // All warps done reading the V tile; prefetch next V.
        if (more) {
            __syncthreads();
            load_v(k0g + 32);
        }
    }

    const float inv0 = 1.0f / l[0], inv1 = 1.0f / l[1];
#pragma unroll
    for (int nt = 0; nt < 16; nt++) {
#pragma unroll
        for (int h = 0; h < 2; h++) {
            float inv = h ? inv1 : inv0;
            float v0 = accO[nt][2 * h] * inv;
            float v1 = accO[nt][2 * h + 1] * inv;
            __nv_bfloat16 h0 = __float2bfloat16(v0);
            __nv_bfloat16 h1 = __float2bfloat16(v1);
            const size_t o = baseO
                + (size_t)(qrow_base + lr + 8 * h) * D_DIM + nt * 8 + lc2;
            *(uint32_t*)(Ohi + o) = packbf2(h0, h1);
            *(uint32_t*)(Olo + o) = packbf2(
                __float2bfloat16(v0 - __bfloat162float(h0)),
                __float2bfloat16(v1 - __bfloat162float(h1)));
        }
    }
}

// ---------------------------------------------------------------------------
// Launch
// Inputs: x, freqs, mask(unused: exactly causal), Wq, Wdown, Wkup, Wvup, Wo
// ---------------------------------------------------------------------------
extern "C" void kernel_launch(void* const* d_in, const int* in_sizes, int n_in,
                              void* d_out, int out_size)
{
    const float* x     = (const float*)d_in[0];
    const float* freqs = (const float*)d_in[1];
    const float* Wq    = (const float*)d_in[3];
    const float* Wdn   = (const float*)d_in[4];
    const float* Wku   = (const float*)d_in[5];
    const float* Wvu   = (const float*)d_in[6];
    const float* Wo    = (const float*)d_in[7];
    float* out = (float*)d_out;

    __nv_bfloat16 *xhi, *xlo, *wthi, *wtlo;
    __nv_bfloat16 *qchi, *qclo, *kvhi, *kvlo, *ohi, *olo;
    float2* cstab;
    cudaGetSymbolAddress((void**)&xhi, g_xhi);
    cudaGetSymbolAddress((void**)&xlo, g_xlo);
    cudaGetSymbolAddress((void**)&qchi, g_qchi);
    cudaGetSymbolAddress((void**)&qclo, g_qclo);
    cudaGetSymbolAddress((void**)&kvhi, g_kvhi);
    cudaGetSymbolAddress((void**)&kvlo, g_kvlo);
    cudaGetSymbolAddress((void**)&ohi, g_ohi);
    cudaGetSymbolAddress((void**)&olo, g_olo);
    cudaGetSymbolAddress((void**)&wthi, g_wthi);
    cudaGetSymbolAddress((void**)&wtlo, g_wtlo);
    cudaGetSymbolAddress((void**)&cstab, g_cs);

    cudaFuncSetAttribute(gemm_hilo_kernel,
                         cudaFuncAttributeMaxDynamicSharedMemorySize, GK_SMEM_DYN);
    cudaFuncSetAttribute(flash_hmma_kernel,
                         cudaFuncAttributeMaxDynamicSharedMemorySize, FL_SMEM);

    // Single batched prep launch: all transposes + x convert + RoPE table.
    prep_kernel<<<PREP_GRID, 256>>>(x, freqs, Wq, Wdn, Wku, Wvu, Wo,
                                    xhi, xlo, wthi, wtlo, cstab);

    // Merged Q|c projection: x @ [Wq|Wdown], N=2560, RoPE on cols < 2048.
    gemm_hilo_kernel<<<GK_GRID, 256, GK_SMEM_DYN>>>(
        xhi, xlo, wthi + OFF_WQ, wtlo + OFF_WQ,
        nullptr, qchi, qclo, cstab, 2048,
        ROWS_TOT, QC_W, D_DIM, D_DIM, QC_W);

    // Merged K|V up-projection: c @ [Wkup|Wvup], N=4096, RoPE on cols < 2048.
    gemm_hilo_kernel<<<GK_GRID, 256, GK_SMEM_DYN>>>(
        qchi + 2048, qclo + 2048, wthi + OFF_WKU, wtlo + OFF_WKU,
        nullptr, kvhi, kvlo, cstab, 2048,
        ROWS_TOT, KV_W, LAT, QC_W, KV_W);

    // Flash attention v3 (causal, HMMA hi/lo, BC=32, 3 CTAs/SM)
    flash_hmma_kernel<<<dim3(S_LEN / 64, BATCH * NH), 128, FL_SMEM>>>(
        qchi, qclo, kvhi, kvlo, ohi, olo);

    // Output projection (fp32 out)
    gemm_hilo_kernel<<<GK_GRID, 256, GK_SMEM_DYN>>>(
        ohi, olo, wthi + OFF_WO, wtlo + OFF_WO,
        out, nullptr, nullptr, nullptr, 0,
        ROWS_TOT, D_DIM, D_DIM, D_DIM, D_DIM);
}